// round 4
// baseline (speedup 1.0000x reference)
#include <cuda_runtime.h>
#include <math.h>

// Problem constants
#define BATCH 8
#define CCH   256
#define HH    64
#define WW    160
#define HW    (HH * WW)           // 10240
#define NTOT  (BATCH * CCH * HW)  // 20,971,520

// Scratch: y = relu(bn(1x1conv(x)))  [b][c][h][w]  (84 MB, static device global)
__device__ float g_y[NTOT];
// Per-channel folded BN constants for stage 1
__device__ float g_s1[CCH];
__device__ float g_b1[CCH];

// ---------------------------------------------------------------------------
// K0: fold stage-1 BN constants
//   y = relu(gemm * s1 + b1), s1 = gamma/sqrt(var+eps), b1 = (conv_b-mean)*s1+beta
// ---------------------------------------------------------------------------
__global__ void k_prep(const float* __restrict__ conv_b,
                       const float* __restrict__ gamma,
                       const float* __restrict__ beta,
                       const float* __restrict__ mean,
                       const float* __restrict__ var) {
    int o = threadIdx.x;
    float s = gamma[o] * rsqrtf(var[o] + 1e-5f);
    g_s1[o] = s;
    g_b1[o] = (conv_b[o] - mean[o]) * s + beta[o];
}

// ---------------------------------------------------------------------------
// K1: SGEMM (128x128 tile, 8x8 microtile, K-tile 8, global->reg prefetch)
//   Y[b][o][n] = relu(s1[o] * (sum_c W[o][c] * X[b][c][n]) + b1[o])
// grid (80, 2, 8), block 256
// ---------------------------------------------------------------------------
__global__ __launch_bounds__(256, 2)
void k_gemm(const float* __restrict__ X, const float* __restrict__ Wm) {
    __shared__ float As[8][132];   // [k][m], 132 pad keeps 16B align + no conflicts
    __shared__ float Bs[8][128];   // [k][n]

    const int b  = blockIdx.z;
    const int m0 = blockIdx.y * 128;
    const int n0 = blockIdx.x * 128;
    const int tid = threadIdx.x;
    const int ty = tid >> 4;       // 0..15 -> output rows ty*8..+7
    const int tx = tid & 15;       // 0..15 -> output cols tx*8..+7

    // A staging: thread loads float4 of W[m0+arow][acg..acg+3] per k-tile
    const int arow = tid >> 1;           // 0..127
    const int acg  = (tid & 1) * 4;      // 0 or 4
    const float* Aptr = Wm + (size_t)(m0 + arow) * CCH + acg;
    // B staging: thread loads float4 of X[b][brow][n0+bcol]
    const int brow = tid >> 5;           // 0..7
    const int bcol = (tid & 31) * 4;
    const float* Bptr = X + ((size_t)b * CCH + brow) * HW + n0 + bcol;

    float4 aReg = *(const float4*)(Aptr);
    float4 bReg = *(const float4*)(Bptr);

    float acc[8][8];
#pragma unroll
    for (int i = 0; i < 8; ++i)
#pragma unroll
        for (int j = 0; j < 8; ++j) acc[i][j] = 0.f;

    for (int kt = 0; kt < 32; ++kt) {
        As[acg + 0][arow] = aReg.x;
        As[acg + 1][arow] = aReg.y;
        As[acg + 2][arow] = aReg.z;
        As[acg + 3][arow] = aReg.w;
        *(float4*)&Bs[brow][bcol] = bReg;
        __syncthreads();

        if (kt < 31) {  // prefetch next k-tile into registers during compute
            aReg = *(const float4*)(Aptr + (kt + 1) * 8);
            bReg = *(const float4*)(Bptr + (size_t)(kt + 1) * 8 * HW);
        }

#pragma unroll
        for (int k = 0; k < 8; ++k) {
            float a[8], bb[8];
            *(float4*)(a)      = *(const float4*)&As[k][ty * 8];
            *(float4*)(a + 4)  = *(const float4*)&As[k][ty * 8 + 4];
            *(float4*)(bb)     = *(const float4*)&Bs[k][tx * 8];
            *(float4*)(bb + 4) = *(const float4*)&Bs[k][tx * 8 + 4];
#pragma unroll
            for (int i = 0; i < 8; ++i)
#pragma unroll
                for (int j = 0; j < 8; ++j)
                    acc[i][j] = fmaf(a[i], bb[j], acc[i][j]);
        }
        __syncthreads();
    }

    // Epilogue: BN + ReLU, write y
#pragma unroll
    for (int i = 0; i < 8; ++i) {
        const int m = m0 + ty * 8 + i;
        const float s = g_s1[m];
        const float t = g_b1[m];
        float* yp = g_y + ((size_t)b * CCH + m) * HW + n0 + tx * 8;
        float4 v0, v1;
        v0.x = fmaxf(fmaf(s, acc[i][0], t), 0.f);
        v0.y = fmaxf(fmaf(s, acc[i][1], t), 0.f);
        v0.z = fmaxf(fmaf(s, acc[i][2], t), 0.f);
        v0.w = fmaxf(fmaf(s, acc[i][3], t), 0.f);
        v1.x = fmaxf(fmaf(s, acc[i][4], t), 0.f);
        v1.y = fmaxf(fmaf(s, acc[i][5], t), 0.f);
        v1.z = fmaxf(fmaf(s, acc[i][6], t), 0.f);
        v1.w = fmaxf(fmaf(s, acc[i][7], t), 0.f);
        *(float4*)(yp)     = v0;
        *(float4*)(yp + 4) = v1;
    }
}

// ---------------------------------------------------------------------------
// K2: fused 12-shift depthwise-3x3 + BN + ReLU + weighted residual sum.
// One block per (b,c) plane; full 64x160 y-plane staged in shared memory.
// Insight: the zero-pad validity mask valid(h+kh-1, w+kw-1) is the SAME for
// all 12 shifts; BN scale rs folds into the 3x3 weights.
//   out = x + sum_s wt'_s * relu( sum g'[kh][kw]*y[(h+kh-1-sh)%H][(w+kw-1-sw)%W] + rb )
// ---------------------------------------------------------------------------
__global__ __launch_bounds__(256, 2)
void k_refine(const float* __restrict__ x,
              const float* __restrict__ rw,     // refine_w [C][1][3][3]
              const float* __restrict__ rbias,  // refine_b
              const float* __restrict__ rg, const float* __restrict__ rbeta,
              const float* __restrict__ rmu, const float* __restrict__ rvar,
              float* __restrict__ out,
              float w1, float w2, float w3) {   // 0.5*exp(-k^2/4.5)/WSUM
    __shared__ float sp[HH * WW];  // 40 KB plane

    const int bc = blockIdx.x;       // = b*256 + c
    const int c  = bc & 255;
    const int tid = threadIdx.x;

    // load plane (coalesced float4)
    {
        const float4* yp4 = (const float4*)(g_y + (size_t)bc * HW);
        float4* sp4 = (float4*)sp;
        for (int i = tid; i < HW / 4; i += 256) sp4[i] = yp4[i];
    }

    // per-channel folded constants
    const float rs  = rg[c] * rsqrtf(rvar[c] + 1e-5f);
    const float rbb = (rbias[c] - rmu[c]) * rs + rbeta[c];
    float g[3][3];
#pragma unroll
    for (int k = 0; k < 9; ++k) ((float*)g)[k] = rs * __ldg(rw + c * 9 + k);
    const float wts[4] = {0.f, w1, w2, w3};

    __syncthreads();

    for (int q = tid; q < HH * (WW / 4); q += 256) {
        const int h  = q / (WW / 4);
        const int wg = q - h * (WW / 4);
        const int w  = wg * 4;
        float acc[4] = {0.f, 0.f, 0.f, 0.f};

        const bool fast = (h >= 1) & (h <= HH - 2) & (wg >= 1) & (wg <= (WW / 4) - 2);
        if (fast) {
            // ---------- vertical shifts (sh in +-1..3), rolling over 9 rows ----------
            float convV[7][4];
#pragma unroll
            for (int s = 0; s < 7; ++s)
#pragma unroll
                for (int j = 0; j < 4; ++j) convV[s][j] = 0.f;

#pragma unroll
            for (int r = 0; r < 9; ++r) {
                const int rr = (h - 4 + r) & (HH - 1);
                const float* rp = sp + rr * WW + (w - 1);
                float rv[6];
#pragma unroll
                for (int cc = 0; cc < 6; ++cc) rv[cc] = rp[cc];
#pragma unroll
                for (int kh = 0; kh < 3; ++kh) {
                    const int s = kh + 3 - r;  // shift value contributed by (r,kh)
                    if (s >= -3 && s <= 3 && s != 0) {
#pragma unroll
                        for (int j = 0; j < 4; ++j) {
                            float t = convV[s + 3][j];
                            t = fmaf(g[kh][0], rv[j],     t);
                            t = fmaf(g[kh][1], rv[j + 1], t);
                            t = fmaf(g[kh][2], rv[j + 2], t);
                            convV[s + 3][j] = t;
                        }
                    }
                }
            }
#pragma unroll
            for (int si = 0; si < 7; ++si) {
                if (si == 3) continue;
                const float wt = wts[si < 3 ? 3 - si : si - 3];
#pragma unroll
                for (int j = 0; j < 4; ++j)
                    acc[j] = fmaf(wt, fmaxf(convV[si][j] + rbb, 0.f), acc[j]);
            }

            // ---------- horizontal shifts (sw in +-1..3), rolling over 12 cols ----------
            float convH[7][4];
#pragma unroll
            for (int s = 0; s < 7; ++s)
#pragma unroll
                for (int j = 0; j < 4; ++j) convH[s][j] = 0.f;

            const float* r0 = sp + (h - 1) * WW;
            const float* r1 = sp + h * WW;
            const float* r2 = sp + (h + 1) * WW;
#pragma unroll
            for (int cc = 0; cc < 12; ++cc) {
                const int ca = w - 4 + cc;
                const float c0 = r0[ca], c1 = r1[ca], c2 = r2[ca];
                const float t0 = fmaf(g[0][0], c0, fmaf(g[1][0], c1, g[2][0] * c2));
                const float t1 = fmaf(g[0][1], c0, fmaf(g[1][1], c1, g[2][1] * c2));
                const float t2 = fmaf(g[0][2], c0, fmaf(g[1][2], c1, g[2][2] * c2));
#pragma unroll
                for (int kw = 0; kw < 3; ++kw) {
                    const float tk = (kw == 0) ? t0 : (kw == 1) ? t1 : t2;
#pragma unroll
                    for (int j = 0; j < 4; ++j) {
                        const int sw = j + kw + 3 - cc;
                        if (sw >= -3 && sw <= 3 && sw != 0)
                            convH[sw + 3][j] += tk;
                    }
                }
            }
#pragma unroll
            for (int si = 0; si < 7; ++si) {
                if (si == 3) continue;
                const float wt = wts[si < 3 ? 3 - si : si - 3];
#pragma unroll
                for (int j = 0; j < 4; ++j)
                    acc[j] = fmaf(wt, fmaxf(convH[si][j] + rbb, 0.f), acc[j]);
            }
        } else {
            // ---------- masked slow path (image border, ~8% of quads) ----------
            const int SHV[12] = {1, 2, 3, -1, -2, -3, 0, 0, 0, 0, 0, 0};
            const int SWV[12] = {0, 0, 0, 0, 0, 0, -1, -2, -3, 1, 2, 3};
            const int AW[12]  = {1, 2, 3, 1, 2, 3, 1, 2, 3, 1, 2, 3};
            const float rv0 = (h >= 1) ? 1.f : 0.f;
            const float rv2 = (h <= HH - 2) ? 1.f : 0.f;
#pragma unroll
            for (int j = 0; j < 4; ++j) {
                const int wj = w + j;
                const float cv0 = (wj >= 1) ? 1.f : 0.f;
                const float cv2 = (wj <= WW - 2) ? 1.f : 0.f;
                float gm[3][3];
#pragma unroll
                for (int kw = 0; kw < 3; ++kw) {
                    const float cv = (kw == 0) ? cv0 : (kw == 2) ? cv2 : 1.f;
                    gm[0][kw] = g[0][kw] * rv0 * cv;
                    gm[1][kw] = g[1][kw] * cv;
                    gm[2][kw] = g[2][kw] * rv2 * cv;
                }
                float a = 0.f;
#pragma unroll
                for (int si = 0; si < 12; ++si) {
                    const int sh = SHV[si], sw = SWV[si];
                    float sum = 0.f;
#pragma unroll
                    for (int kh = 0; kh < 3; ++kh) {
#pragma unroll
                        for (int kw = 0; kw < 3; ++kw) {
                            const int rr = (h + kh - 1 - sh) & (HH - 1);
                            int ccol = wj + kw - 1 - sw;
                            if (ccol < 0) ccol += WW;
                            if (ccol >= WW) ccol -= WW;
                            sum = fmaf(gm[kh][kw], sp[rr * WW + ccol], sum);
                        }
                    }
                    a = fmaf(wts[AW[si]], fmaxf(sum + rbb, 0.f), a);
                }
                acc[j] = a;
            }
        }

        const size_t base = (size_t)bc * HW + h * WW + w;
        const float4 xv = *(const float4*)(x + base);
        float4 o4;
        o4.x = xv.x + acc[0];
        o4.y = xv.y + acc[1];
        o4.z = xv.z + acc[2];
        o4.w = xv.w + acc[3];
        *(float4*)(out + base) = o4;
    }
}

// ---------------------------------------------------------------------------
extern "C" void kernel_launch(void* const* d_in, const int* in_sizes, int n_in,
                              void* d_out, int out_size) {
    const float* x        = (const float*)d_in[0];
    const float* conv_w   = (const float*)d_in[1];
    const float* conv_b   = (const float*)d_in[2];
    const float* bn_gamma = (const float*)d_in[3];
    const float* bn_beta  = (const float*)d_in[4];
    const float* bn_mean  = (const float*)d_in[5];
    const float* bn_var   = (const float*)d_in[6];
    const float* refine_w = (const float*)d_in[7];
    const float* refine_b = (const float*)d_in[8];
    const float* rbn_gamma = (const float*)d_in[9];
    const float* rbn_beta  = (const float*)d_in[10];
    const float* rbn_mean  = (const float*)d_in[11];
    const float* rbn_var   = (const float*)d_in[12];
    float* out = (float*)d_out;

    // shift weights: exp(-k^2/(2*1.5^2)), WSUM = 4*(w1+w2+w3); fold 0.5/WSUM
    const double s2 = 2.0 * 1.5 * 1.5;
    const double e1 = exp(-1.0 / s2), e2 = exp(-4.0 / s2), e3 = exp(-9.0 / s2);
    const double wsum = 4.0 * (e1 + e2 + e3);
    const float w1 = (float)(0.5 * e1 / wsum);
    const float w2 = (float)(0.5 * e2 / wsum);
    const float w3 = (float)(0.5 * e3 / wsum);

    k_prep<<<1, CCH>>>(conv_b, bn_gamma, bn_beta, bn_mean, bn_var);

    dim3 g1(HW / 128, CCH / 128, BATCH);  // (80, 2, 8)
    k_gemm<<<g1, 256>>>(x, conv_w);

    k_refine<<<BATCH * CCH, 256>>>(x, refine_w, refine_b,
                                   rbn_gamma, rbn_beta, rbn_mean, rbn_var,
                                   out, w1, w2, w3);
}

// round 6
// speedup vs baseline: 1.5451x; 1.5451x over previous
#include <cuda_runtime.h>
#include <math.h>
#include <cstdint>

// Problem constants
#define BATCH 8
#define CCH   256
#define HH    64
#define WW    160
#define HW    (HH * WW)           // 10240
#define NTOT  (BATCH * CCH * HW)  // 20,971,520

// Scratch
__device__ float g_y[NTOT];          // y = relu(bn(1x1conv(x)))
__device__ float g_wt[CCH * CCH];    // tf32(s1[m] * W[m][k]) stored [k][m]
__device__ float g_b1[CCH];          // folded BN bias

// ---------------------------------------------------------------------------
__device__ __forceinline__ uint32_t smem_u32(const void* p) {
    uint32_t a;
    asm("{ .reg .u64 t; cvta.to.shared.u64 t, %1; cvt.u32.u64 %0, t; }"
        : "=r"(a) : "l"(p));
    return a;
}
__device__ __forceinline__ float tf32r(float x) {
    asm("cvt.rna.tf32.f32 %0, %1;" : "=f"(x) : "f"(x));
    return x;
}
__device__ __forceinline__ void cp16(uint32_t s, const void* g) {
    asm volatile("cp.async.cg.shared.global [%0], [%1], 16;" :: "r"(s), "l"(g));
}

// ---------------------------------------------------------------------------
// K0: fold BN into W: g_wt[k][m] = tf32(s1[m]*W[m][k]); g_b1[m]
// ---------------------------------------------------------------------------
__global__ void k_tw(const float* __restrict__ W, const float* __restrict__ conv_b,
                     const float* __restrict__ gamma, const float* __restrict__ beta,
                     const float* __restrict__ mean, const float* __restrict__ var) {
    const int m = blockIdx.x, k = threadIdx.x;
    const float s = gamma[m] * rsqrtf(var[m] + 1e-5f);
    g_wt[k * CCH + m] = tf32r(s * W[m * CCH + k]);
    if (k == 0) g_b1[m] = (conv_b[m] - mean[m]) * s + beta[m];
}

// ---------------------------------------------------------------------------
// K1: tf32 mma.sync GEMM + fused bias + ReLU
//   y[b][m][n] = relu( sum_k g_wt[k][m]*X[b][k][n] + b1[m] )
// BM=256 (all M, X read once), BN=64, BK=32; 8 warps as 4(m) x 2(n),
// warp tile 64x32 = 4x4 frags of m16n8k8. A via cp.async double-buffer,
// B via register prefetch + tf32 cvt. grid (160, 8), block 256.
// ---------------------------------------------------------------------------
#define BK   32
#define BN   64
#define APAD 264          // 256+8: banks (8k+m)%32 distinct for frag loads
#define BPAD 72           // 64+8
#define ASZ  (BK * APAD)
#define BSZ  (BK * BPAD)
#define GEMM_SMEM ((2 * ASZ + 2 * BSZ) * 4)   // 86016 B

__global__ __launch_bounds__(256, 2)
void k_gemm(const float* __restrict__ X) {
    extern __shared__ float smg[];
    float* As = smg;               // 2 buffers [BK][APAD]
    float* Bs = smg + 2 * ASZ;     // 2 buffers [BK][BPAD]
    const int tid = threadIdx.x;
    const int wid = tid >> 5, lane = tid & 31;
    const int n0 = blockIdx.x * BN;
    const int b  = blockIdx.y;
    const uint32_t smbA = smem_u32(As);
    const float* Xb = X + (size_t)b * CCH * HW;

    // prologue: A tile 0 (cp.async), B tile 0 (regs)
#pragma unroll
    for (int i = 0; i < 8; ++i) {
        const int idx = tid + i * 256;
        const int row = idx >> 6, c4 = idx & 63;
        cp16(smbA + (row * APAD + c4 * 4) * 4, g_wt + row * CCH + c4 * 4);
    }
    asm volatile("cp.async.commit_group;" ::: "memory");
    float4 breg[2];
#pragma unroll
    for (int i = 0; i < 2; ++i) {
        const int idx = tid + i * 256;
        const int row = idx >> 4, c4 = idx & 15;
        breg[i] = *(const float4*)(Xb + (size_t)row * HW + n0 + c4 * 4);
    }

    float acc[4][4][4];
#pragma unroll
    for (int im = 0; im < 4; ++im)
#pragma unroll
        for (int in = 0; in < 4; ++in)
#pragma unroll
            for (int r = 0; r < 4; ++r) acc[im][in][r] = 0.f;

    const int mw = wid >> 1, nw = wid & 1;
    const int lr = lane >> 2, lc = lane & 3;

    for (int kc = 0; kc < 8; ++kc) {
        const int bf = kc & 1;
        asm volatile("cp.async.wait_group 0;" ::: "memory");
        // store B tile (tf32 rounded)
        float* Bb = Bs + bf * BSZ;
#pragma unroll
        for (int i = 0; i < 2; ++i) {
            const int idx = tid + i * 256;
            const int row = idx >> 4, c4 = idx & 15;
            float4 v = breg[i];
            v.x = tf32r(v.x); v.y = tf32r(v.y); v.z = tf32r(v.z); v.w = tf32r(v.w);
            *(float4*)(Bb + row * BPAD + c4 * 4) = v;
        }
        __syncthreads();
        if (kc < 7) {
            const uint32_t dstb = smbA + ((bf ^ 1) * ASZ) * 4;
#pragma unroll
            for (int i = 0; i < 8; ++i) {
                const int idx = tid + i * 256;
                const int row = idx >> 6, c4 = idx & 63;
                cp16(dstb + (row * APAD + c4 * 4) * 4,
                     g_wt + ((kc + 1) * BK + row) * CCH + c4 * 4);
            }
            asm volatile("cp.async.commit_group;" ::: "memory");
#pragma unroll
            for (int i = 0; i < 2; ++i) {
                const int idx = tid + i * 256;
                const int row = idx >> 4, c4 = idx & 15;
                breg[i] = *(const float4*)(Xb + (size_t)((kc + 1) * BK + row) * HW
                                           + n0 + c4 * 4);
            }
        }
        // compute
        const float* Ab  = As + bf * ASZ + lc * APAD + mw * 64 + lr;
        const float* Bbf = Bs + bf * BSZ + lc * BPAD + nw * 32 + lr;
#pragma unroll
        for (int ks = 0; ks < 4; ++ks) {
            const float* Ak = Ab + ks * 8 * APAD;
            const float* Bk = Bbf + ks * 8 * BPAD;
            uint32_t a[4][4], bb[4][2];
#pragma unroll
            for (int im = 0; im < 4; ++im) {
                a[im][0] = *(const uint32_t*)(Ak + im * 16);
                a[im][1] = *(const uint32_t*)(Ak + im * 16 + 8);
                a[im][2] = *(const uint32_t*)(Ak + im * 16 + 4 * APAD);
                a[im][3] = *(const uint32_t*)(Ak + im * 16 + 8 + 4 * APAD);
            }
#pragma unroll
            for (int in = 0; in < 4; ++in) {
                bb[in][0] = *(const uint32_t*)(Bk + in * 8);
                bb[in][1] = *(const uint32_t*)(Bk + in * 8 + 4 * BPAD);
            }
#pragma unroll
            for (int im = 0; im < 4; ++im)
#pragma unroll
                for (int in = 0; in < 4; ++in) {
                    asm volatile(
                        "mma.sync.aligned.m16n8k8.row.col.f32.tf32.tf32.f32 "
                        "{%0,%1,%2,%3}, {%4,%5,%6,%7}, {%8,%9}, {%0,%1,%2,%3};"
                        : "+f"(acc[im][in][0]), "+f"(acc[im][in][1]),
                          "+f"(acc[im][in][2]), "+f"(acc[im][in][3])
                        : "r"(a[im][0]), "r"(a[im][1]), "r"(a[im][2]), "r"(a[im][3]),
                          "r"(bb[in][0]), "r"(bb[in][1]));
                }
        }
        __syncthreads();
    }

    // epilogue: bias + ReLU -> g_y
#pragma unroll
    for (int im = 0; im < 4; ++im) {
        const int r0 = mw * 64 + im * 16 + lr;
        const float bz0 = g_b1[r0], bz1 = g_b1[r0 + 8];
#pragma unroll
        for (int in = 0; in < 4; ++in) {
            const int nc = n0 + nw * 32 + in * 8 + lc * 2;
            float* p0 = g_y + ((size_t)(b * CCH + r0)) * HW + nc;
            float* p1 = p0 + (size_t)8 * HW;
            float2 v0, v1;
            v0.x = fmaxf(acc[im][in][0] + bz0, 0.f);
            v0.y = fmaxf(acc[im][in][1] + bz0, 0.f);
            v1.x = fmaxf(acc[im][in][2] + bz1, 0.f);
            v1.y = fmaxf(acc[im][in][3] + bz1, 0.f);
            *(float2*)p0 = v0;
            *(float2*)p1 = v1;
        }
    }
}

// ---------------------------------------------------------------------------
// K2: refine via circular-conv factorization.
//   z = relu(conv_circ(y) + rbb)  (once per plane)
//   interior:  out = x + sum_s wt_s * z[(h-sh)%H][(w-sw)%W]
//   border:    masked slow path (R3-validated)
// smem: sp (y plane) + zp (z plane) = 80 KB dynamic. grid 2048, block 256.
// ---------------------------------------------------------------------------
#define REFINE_SMEM (2 * HW * 4)

__global__ __launch_bounds__(256, 2)
void k_refine(const float* __restrict__ x,
              const float* __restrict__ rw, const float* __restrict__ rbias,
              const float* __restrict__ rg, const float* __restrict__ rbeta,
              const float* __restrict__ rmu, const float* __restrict__ rvar,
              float* __restrict__ out,
              float w1, float w2, float w3) {
    extern __shared__ float smr[];
    float* sp = smr;        // y plane
    float* zp = smr + HW;   // z plane

    const int bc = blockIdx.x;
    const int c  = bc & 255;
    const int tid = threadIdx.x;

    {
        const float4* yp4 = (const float4*)(g_y + (size_t)bc * HW);
        float4* sp4 = (float4*)sp;
        for (int i = tid; i < HW / 4; i += 256) sp4[i] = yp4[i];
    }
    const float rs  = rg[c] * rsqrtf(rvar[c] + 1e-5f);
    const float rbb = (rbias[c] - rmu[c]) * rs + rbeta[c];
    float g[3][3];
#pragma unroll
    for (int k = 0; k < 9; ++k) ((float*)g)[k] = rs * __ldg(rw + c * 9 + k);
    const float wts[4] = {0.f, w1, w2, w3};
    __syncthreads();

    // ---- phase Z: circular 3x3 conv + bias + relu ----
    for (int q = tid; q < HW / 4; q += 256) {
        const int h = q / (WW / 4);
        const int wg = q - h * (WW / 4);
        const int w = wg * 4;
        const int rm = (h + HH - 1) & (HH - 1);
        const int rp = (h + 1) & (HH - 1);
        float rv[3][6];
        if (wg >= 1 && wg <= (WW / 4) - 2) {
            const float* p0 = sp + rm * WW + w - 1;
            const float* p1 = sp + h * WW + w - 1;
            const float* p2 = sp + rp * WW + w - 1;
#pragma unroll
            for (int cc = 0; cc < 6; ++cc) {
                rv[0][cc] = p0[cc]; rv[1][cc] = p1[cc]; rv[2][cc] = p2[cc];
            }
        } else {
#pragma unroll
            for (int cc = 0; cc < 6; ++cc) {
                int col = w - 1 + cc;
                col = (col + WW) % WW;
                rv[0][cc] = sp[rm * WW + col];
                rv[1][cc] = sp[h * WW + col];
                rv[2][cc] = sp[rp * WW + col];
            }
        }
        float4 z;
#pragma unroll
        for (int j = 0; j < 4; ++j) {
            const float c0 = fmaf(g[0][0], rv[0][j],
                             fmaf(g[1][0], rv[1][j], g[2][0] * rv[2][j]));
            const float c1 = fmaf(g[0][1], rv[0][j + 1],
                             fmaf(g[1][1], rv[1][j + 1], g[2][1] * rv[2][j + 1]));
            const float c2 = fmaf(g[0][2], rv[0][j + 2],
                             fmaf(g[1][2], rv[1][j + 2], g[2][2] * rv[2][j + 2]));
            ((float*)&z)[j] = fmaxf(c0 + c1 + c2 + rbb, 0.f);
        }
        *(float4*)(zp + h * WW + w) = z;
    }
    __syncthreads();

    // ---- phase ACC ----
    for (int q = tid; q < HW / 4; q += 256) {
        const int h = q / (WW / 4);
        const int wg = q - h * (WW / 4);
        const int w = wg * 4;
        float acc[4] = {0.f, 0.f, 0.f, 0.f};

        if (h >= 1 && h <= HH - 2 && wg >= 1 && wg <= (WW / 4) - 2) {
            // vertical shifts +-1..3
#pragma unroll
            for (int s = 1; s <= 3; ++s) {
                const float wt = wts[s];
                const float4 u = *(const float4*)(zp + ((h - s) & (HH - 1)) * WW + w);
                const float4 d = *(const float4*)(zp + ((h + s) & (HH - 1)) * WW + w);
                acc[0] = fmaf(wt, u.x + d.x, acc[0]);
                acc[1] = fmaf(wt, u.y + d.y, acc[1]);
                acc[2] = fmaf(wt, u.z + d.z, acc[2]);
                acc[3] = fmaf(wt, u.w + d.w, acc[3]);
            }
            // horizontal shifts +-1..3
            float zr[12];
            *(float4*)(zr)     = *(const float4*)(zp + h * WW + w - 4);
            *(float4*)(zr + 4) = *(const float4*)(zp + h * WW + w);
            *(float4*)(zr + 8) = *(const float4*)(zp + h * WW + w + 4);
#pragma unroll
            for (int s = 1; s <= 3; ++s) {
                const float wt = wts[s];
#pragma unroll
                for (int j = 0; j < 4; ++j)
                    acc[j] = fmaf(wt, zr[4 + j - s] + zr[4 + j + s], acc[j]);
            }
        } else {
            const int SHV[12] = {1, 2, 3, -1, -2, -3, 0, 0, 0, 0, 0, 0};
            const int SWV[12] = {0, 0, 0, 0, 0, 0, -1, -2, -3, 1, 2, 3};
            const int AW[12]  = {1, 2, 3, 1, 2, 3, 1, 2, 3, 1, 2, 3};
#pragma unroll
            for (int j = 0; j < 4; ++j) {
                const int wj = w + j;
                if (h >= 1 && h <= HH - 2 && wj >= 1 && wj <= WW - 2) {
                    // interior pixel inside a border quad: scalar z-sum
                    float a = 0.f;
#pragma unroll
                    for (int s = 1; s <= 3; ++s) {
                        const float wt = wts[s];
                        a = fmaf(wt, zp[((h - s) & (HH - 1)) * WW + wj] +
                                     zp[((h + s) & (HH - 1)) * WW + wj], a);
                        int cl = wj - s; if (cl < 0) cl += WW;
                        int cr = wj + s; if (cr >= WW) cr -= WW;
                        a = fmaf(wt, zp[h * WW + cl] + zp[h * WW + cr], a);
                    }
                    acc[j] = a;
                } else {
                    // true border pixel: masked conv from sp
                    const float rv0 = (h >= 1) ? 1.f : 0.f;
                    const float rv2 = (h <= HH - 2) ? 1.f : 0.f;
                    const float cv0 = (wj >= 1) ? 1.f : 0.f;
                    const float cv2 = (wj <= WW - 2) ? 1.f : 0.f;
                    float gm[3][3];
#pragma unroll
                    for (int kw = 0; kw < 3; ++kw) {
                        const float cv = (kw == 0) ? cv0 : (kw == 2) ? cv2 : 1.f;
                        gm[0][kw] = g[0][kw] * rv0 * cv;
                        gm[1][kw] = g[1][kw] * cv;
                        gm[2][kw] = g[2][kw] * rv2 * cv;
                    }
                    float a = 0.f;
#pragma unroll
                    for (int si = 0; si < 12; ++si) {
                        const int sh = SHV[si], sw = SWV[si];
                        float sum = 0.f;
#pragma unroll
                        for (int kh = 0; kh < 3; ++kh)
#pragma unroll
                            for (int kw = 0; kw < 3; ++kw) {
                                const int rr = (h + kh - 1 - sh) & (HH - 1);
                                int ccol = wj + kw - 1 - sw;
                                if (ccol < 0) ccol += WW;
                                if (ccol >= WW) ccol -= WW;
                                sum = fmaf(gm[kh][kw], sp[rr * WW + ccol], sum);
                            }
                        a = fmaf(wts[AW[si]], fmaxf(sum + rbb, 0.f), a);
                    }
                    acc[j] = a;
                }
            }
        }

        const size_t base = (size_t)bc * HW + h * WW + w;
        const float4 xv = *(const float4*)(x + base);
        float4 o4;
        o4.x = xv.x + acc[0];
        o4.y = xv.y + acc[1];
        o4.z = xv.z + acc[2];
        o4.w = xv.w + acc[3];
        *(float4*)(out + base) = o4;
    }
}

// ---------------------------------------------------------------------------
extern "C" void kernel_launch(void* const* d_in, const int* in_sizes, int n_in,
                              void* d_out, int out_size) {
    const float* x        = (const float*)d_in[0];
    const float* conv_w   = (const float*)d_in[1];
    const float* conv_b   = (const float*)d_in[2];
    const float* bn_gamma = (const float*)d_in[3];
    const float* bn_beta  = (const float*)d_in[4];
    const float* bn_mean  = (const float*)d_in[5];
    const float* bn_var   = (const float*)d_in[6];
    const float* refine_w = (const float*)d_in[7];
    const float* refine_b = (const float*)d_in[8];
    const float* rbn_gamma = (const float*)d_in[9];
    const float* rbn_beta  = (const float*)d_in[10];
    const float* rbn_mean  = (const float*)d_in[11];
    const float* rbn_var   = (const float*)d_in[12];
    float* out = (float*)d_out;

    const double s2 = 2.0 * 1.5 * 1.5;
    const double e1 = exp(-1.0 / s2), e2 = exp(-4.0 / s2), e3 = exp(-9.0 / s2);
    const double wsum = 4.0 * (e1 + e2 + e3);
    const float w1 = (float)(0.5 * e1 / wsum);
    const float w2 = (float)(0.5 * e2 / wsum);
    const float w3 = (float)(0.5 * e3 / wsum);

    cudaFuncSetAttribute(k_gemm, cudaFuncAttributeMaxDynamicSharedMemorySize,
                         GEMM_SMEM);
    cudaFuncSetAttribute(k_refine, cudaFuncAttributeMaxDynamicSharedMemorySize,
                         REFINE_SMEM);

    k_tw<<<CCH, CCH>>>(conv_w, conv_b, bn_gamma, bn_beta, bn_mean, bn_var);

    dim3 gg(HW / BN, BATCH);   // (160, 8)
    k_gemm<<<gg, 256, GEMM_SMEM>>>(x);

    k_refine<<<BATCH * CCH, 256, REFINE_SMEM>>>(x, refine_w, refine_b,
                                                rbn_gamma, rbn_beta, rbn_mean,
                                                rbn_var, out, w1, w2, w3);
}

// round 7
// speedup vs baseline: 2.2941x; 1.4848x over previous
#include <cuda_runtime.h>
#include <math.h>
#include <cstdint>

// Problem constants
#define BATCH 8
#define CCH   256
#define HH    64
#define WW    160
#define HW    (HH * WW)           // 10240
#define NTOT  (BATCH * CCH * HW)  // 20,971,520
#define NQ    (WW / 4)            // 40 quads per row

// Scratch
__device__ float g_y[NTOT];          // y = relu(bn(1x1conv(x)))
__device__ float g_wt[CCH * CCH];    // tf32(s1[m] * W[m][k]) stored [k][m]
__device__ float g_b1[CCH];          // folded BN bias

// ---------------------------------------------------------------------------
__device__ __forceinline__ uint32_t smem_u32(const void* p) {
    uint32_t a;
    asm("{ .reg .u64 t; cvta.to.shared.u64 t, %1; cvt.u32.u64 %0, t; }"
        : "=r"(a) : "l"(p));
    return a;
}
__device__ __forceinline__ float tf32r(float x) {
    asm("cvt.rna.tf32.f32 %0, %1;" : "=f"(x) : "f"(x));
    return x;
}
__device__ __forceinline__ void cp16(uint32_t s, const void* g) {
    asm volatile("cp.async.cg.shared.global [%0], [%1], 16;" :: "r"(s), "l"(g));
}

// ---------------------------------------------------------------------------
// K0: fold BN into W: g_wt[k][m] = tf32(s1[m]*W[m][k]); g_b1[m]
// ---------------------------------------------------------------------------
__global__ void k_tw(const float* __restrict__ W, const float* __restrict__ conv_b,
                     const float* __restrict__ gamma, const float* __restrict__ beta,
                     const float* __restrict__ mean, const float* __restrict__ var) {
    const int m = blockIdx.x, k = threadIdx.x;
    const float s = gamma[m] * rsqrtf(var[m] + 1e-5f);
    g_wt[k * CCH + m] = tf32r(s * W[m * CCH + k]);
    if (k == 0) g_b1[m] = (conv_b[m] - mean[m]) * s + beta[m];
}

// ---------------------------------------------------------------------------
// K1: tf32 mma.sync GEMM + fused bias + ReLU
//   y[b][m][n] = relu( sum_k g_wt[k][m]*X[b][k][n] + b1[m] )
// BM=256 (all M, X read once), BN=64, BK=32; 8 warps 4(m) x 2(n),
// warp tile 64x32 = 4x4 frags of m16n8k8.
// BOTH A and B stream via cp.async (B fed as raw fp32 bits = truncated tf32)
// => no register prefetch buffers, no spills. grid (160, 8), block 256.
// ---------------------------------------------------------------------------
#define BK   32
#define BN   64
#define APAD 264
#define BPAD 72
#define ASZ  (BK * APAD)
#define BSZ  (BK * BPAD)
#define GEMM_SMEM ((2 * ASZ + 2 * BSZ) * 4)   // 86016 B

__global__ __launch_bounds__(256, 2)
void k_gemm(const float* __restrict__ X) {
    extern __shared__ float smg[];
    float* As = smg;               // 2 buffers [BK][APAD]
    float* Bs = smg + 2 * ASZ;     // 2 buffers [BK][BPAD]
    const int tid = threadIdx.x;
    const int wid = tid >> 5, lane = tid & 31;
    const int n0 = blockIdx.x * BN;
    const int b  = blockIdx.y;
    const uint32_t smbA = smem_u32(As);
    const uint32_t smbB = smem_u32(Bs);
    const float* Xb = X + (size_t)b * CCH * HW;

    // ---- prologue: stage tile 0 ----
#pragma unroll
    for (int i = 0; i < 8; ++i) {
        const int idx = tid + i * 256;
        const int row = idx >> 6, c4 = idx & 63;
        cp16(smbA + (row * APAD + c4 * 4) * 4, g_wt + row * CCH + c4 * 4);
    }
#pragma unroll
    for (int i = 0; i < 2; ++i) {
        const int idx = tid + i * 256;
        const int row = idx >> 4, c4 = idx & 15;
        cp16(smbB + (row * BPAD + c4 * 4) * 4,
             Xb + (size_t)row * HW + n0 + c4 * 4);
    }
    asm volatile("cp.async.commit_group;" ::: "memory");

    float acc[4][4][4];
#pragma unroll
    for (int im = 0; im < 4; ++im)
#pragma unroll
        for (int in = 0; in < 4; ++in)
#pragma unroll
            for (int r = 0; r < 4; ++r) acc[im][in][r] = 0.f;

    const int mw = wid >> 1, nw = wid & 1;
    const int lr = lane >> 2, lc = lane & 3;

    for (int kc = 0; kc < 8; ++kc) {
        const int bf = kc & 1;
        asm volatile("cp.async.wait_group 0;" ::: "memory");
        __syncthreads();

        if (kc < 7) {   // stage tile kc+1 into the other buffer
            const uint32_t dA = smbA + ((bf ^ 1) * ASZ) * 4;
            const uint32_t dB = smbB + ((bf ^ 1) * BSZ) * 4;
#pragma unroll
            for (int i = 0; i < 8; ++i) {
                const int idx = tid + i * 256;
                const int row = idx >> 6, c4 = idx & 63;
                cp16(dA + (row * APAD + c4 * 4) * 4,
                     g_wt + ((kc + 1) * BK + row) * CCH + c4 * 4);
            }
#pragma unroll
            for (int i = 0; i < 2; ++i) {
                const int idx = tid + i * 256;
                const int row = idx >> 4, c4 = idx & 15;
                cp16(dB + (row * BPAD + c4 * 4) * 4,
                     Xb + (size_t)((kc + 1) * BK + row) * HW + n0 + c4 * 4);
            }
            asm volatile("cp.async.commit_group;" ::: "memory");
        }

        const float* Ab  = As + bf * ASZ + lc * APAD + mw * 64 + lr;
        const float* Bbf = Bs + bf * BSZ + lc * BPAD + nw * 32 + lr;
#pragma unroll
        for (int ks = 0; ks < 4; ++ks) {
            const float* Ak = Ab + ks * 8 * APAD;
            const float* Bk = Bbf + ks * 8 * BPAD;
            uint32_t a[4][4], bb[4][2];
#pragma unroll
            for (int im = 0; im < 4; ++im) {
                a[im][0] = *(const uint32_t*)(Ak + im * 16);
                a[im][1] = *(const uint32_t*)(Ak + im * 16 + 8);
                a[im][2] = *(const uint32_t*)(Ak + im * 16 + 4 * APAD);
                a[im][3] = *(const uint32_t*)(Ak + im * 16 + 8 + 4 * APAD);
            }
#pragma unroll
            for (int in = 0; in < 4; ++in) {
                bb[in][0] = *(const uint32_t*)(Bk + in * 8);
                bb[in][1] = *(const uint32_t*)(Bk + in * 8 + 4 * BPAD);
            }
#pragma unroll
            for (int im = 0; im < 4; ++im)
#pragma unroll
                for (int in = 0; in < 4; ++in) {
                    asm volatile(
                        "mma.sync.aligned.m16n8k8.row.col.f32.tf32.tf32.f32 "
                        "{%0,%1,%2,%3}, {%4,%5,%6,%7}, {%8,%9}, {%0,%1,%2,%3};"
                        : "+f"(acc[im][in][0]), "+f"(acc[im][in][1]),
                          "+f"(acc[im][in][2]), "+f"(acc[im][in][3])
                        : "r"(a[im][0]), "r"(a[im][1]), "r"(a[im][2]), "r"(a[im][3]),
                          "r"(bb[in][0]), "r"(bb[in][1]));
                }
        }
        __syncthreads();
    }

    // epilogue: bias + ReLU -> g_y
#pragma unroll
    for (int im = 0; im < 4; ++im) {
        const int r0 = mw * 64 + im * 16 + lr;
        const float bz0 = g_b1[r0], bz1 = g_b1[r0 + 8];
#pragma unroll
        for (int in = 0; in < 4; ++in) {
            const int nc = n0 + nw * 32 + in * 8 + lc * 2;
            float* p0 = g_y + ((size_t)(b * CCH + r0)) * HW + nc;
            float* p1 = p0 + (size_t)8 * HW;
            float2 v0, v1;
            v0.x = fmaxf(acc[im][in][0] + bz0, 0.f);
            v0.y = fmaxf(acc[im][in][1] + bz0, 0.f);
            v1.x = fmaxf(acc[im][in][2] + bz1, 0.f);
            v1.y = fmaxf(acc[im][in][3] + bz1, 0.f);
            *(float2*)p0 = v0;
            *(float2*)p1 = v1;
        }
    }
}

// ---------------------------------------------------------------------------
// K2: refine via circular-conv factorization, conflict-free LDS.128 version.
//   phase Z:   z = relu(circ_conv3x3(y) + rbb)          (uniform, index-wrapped)
//   phase ACC: out = x + sum_s wt_s * z[shifted]        (uniform; border stores
//                                                        predicated off)
//   phase BORDER: 444 true-border px recomputed with the masked formula.
// ---------------------------------------------------------------------------
#define REFINE_SMEM (2 * HW * 4)

__global__ __launch_bounds__(256, 2)
void k_refine(const float* __restrict__ x,
              const float* __restrict__ rw, const float* __restrict__ rbias,
              const float* __restrict__ rg, const float* __restrict__ rbeta,
              const float* __restrict__ rmu, const float* __restrict__ rvar,
              float* __restrict__ out,
              float w1, float w2, float w3) {
    extern __shared__ float smr[];
    float* sp = smr;        // y plane
    float* zp = smr + HW;   // z plane
    const float4* sp4 = (const float4*)sp;
    float4* zp4 = (float4*)zp;

    const int bc = blockIdx.x;
    const int c  = bc & 255;
    const int tid = threadIdx.x;

    {
        const float4* yp4 = (const float4*)(g_y + (size_t)bc * HW);
        float4* d4 = (float4*)sp;
        for (int i = tid; i < HW / 4; i += 256) d4[i] = yp4[i];
    }
    const float rs  = rg[c] * rsqrtf(rvar[c] + 1e-5f);
    const float rbb = (rbias[c] - rmu[c]) * rs + rbeta[c];
    float g[3][3];
#pragma unroll
    for (int k = 0; k < 9; ++k) ((float*)g)[k] = rs * __ldg(rw + c * 9 + k);
    const float wts[4] = {0.f, w1, w2, w3};
    __syncthreads();

    // ---- phase Z: circular 3x3 conv + bias + relu (aligned LDS.128 only) ----
    for (int q = tid; q < HW / 4; q += 256) {
        const int h  = q / NQ;
        const int wq = q - h * NQ;
        const int hm = (h + HH - 1) & (HH - 1);
        const int hp = (h + 1) & (HH - 1);
        const int ql = (wq == 0) ? NQ - 1 : wq - 1;
        const int qr = (wq == NQ - 1) ? 0 : wq + 1;
        const int rows[3] = {hm, h, hp};
        float z[4] = {rbb, rbb, rbb, rbb};
#pragma unroll
        for (int r = 0; r < 3; ++r) {
            const float4 L = sp4[rows[r] * NQ + ql];
            const float4 C = sp4[rows[r] * NQ + wq];
            const float4 R = sp4[rows[r] * NQ + qr];
            const float w6[6] = {L.w, C.x, C.y, C.z, C.w, R.x};
#pragma unroll
            for (int j = 0; j < 4; ++j) {
                z[j] = fmaf(g[r][0], w6[j],     z[j]);
                z[j] = fmaf(g[r][1], w6[j + 1], z[j]);
                z[j] = fmaf(g[r][2], w6[j + 2], z[j]);
            }
        }
        float4 zo;
        zo.x = fmaxf(z[0], 0.f); zo.y = fmaxf(z[1], 0.f);
        zo.z = fmaxf(z[2], 0.f); zo.w = fmaxf(z[3], 0.f);
        zp4[h * NQ + wq] = zo;
    }
    __syncthreads();

    // ---- phase ACC (uniform; skip stores for border px) ----
    for (int q = tid; q < HW / 4; q += 256) {
        const int h  = q / NQ;
        const int wq = q - h * NQ;
        const int w  = wq * 4;
        float acc[4] = {0.f, 0.f, 0.f, 0.f};
#pragma unroll
        for (int s = 1; s <= 3; ++s) {
            const float wt = wts[s];
            const float4 u = zp4[((h - s) & (HH - 1)) * NQ + wq];
            const float4 d = zp4[((h + s) & (HH - 1)) * NQ + wq];
            acc[0] = fmaf(wt, u.x + d.x, acc[0]);
            acc[1] = fmaf(wt, u.y + d.y, acc[1]);
            acc[2] = fmaf(wt, u.z + d.z, acc[2]);
            acc[3] = fmaf(wt, u.w + d.w, acc[3]);
        }
        {
            const int ql = (wq == 0) ? NQ - 1 : wq - 1;
            const int qr = (wq == NQ - 1) ? 0 : wq + 1;
            float zr[12];
            *(float4*)(zr)     = zp4[h * NQ + ql];
            *(float4*)(zr + 4) = zp4[h * NQ + wq];
            *(float4*)(zr + 8) = zp4[h * NQ + qr];
#pragma unroll
            for (int s = 1; s <= 3; ++s) {
                const float wt = wts[s];
#pragma unroll
                for (int j = 0; j < 4; ++j)
                    acc[j] = fmaf(wt, zr[4 + j - s] + zr[4 + j + s], acc[j]);
            }
        }
        const size_t base = (size_t)bc * HW + h * WW + w;
        const float4 xv = *(const float4*)(x + base);
        float4 o4;
        o4.x = xv.x + acc[0]; o4.y = xv.y + acc[1];
        o4.z = xv.z + acc[2]; o4.w = xv.w + acc[3];
        if (h >= 1 && h <= HH - 2 && wq >= 1 && wq <= NQ - 2) {
            *(float4*)(out + base) = o4;
        } else {
#pragma unroll
            for (int j = 0; j < 4; ++j) {
                const int wj = w + j;
                if (h >= 1 && h <= HH - 2 && wj >= 1 && wj <= WW - 2)
                    out[base + j] = ((const float*)&o4)[j];
            }
        }
    }

    // ---- phase BORDER: 444 true-border px, masked formula (validated) ----
    for (int i = tid; i < 2 * WW + 2 * (HH - 2); i += 256) {
        int h, wj;
        if (i < 2 * WW) { h = (i < WW) ? 0 : HH - 1; wj = (i < WW) ? i : i - WW; }
        else { const int j = i - 2 * WW; h = 1 + (j >> 1); wj = (j & 1) ? WW - 1 : 0; }

        const int SHV[12] = {1, 2, 3, -1, -2, -3, 0, 0, 0, 0, 0, 0};
        const int SWV[12] = {0, 0, 0, 0, 0, 0, -1, -2, -3, 1, 2, 3};
        const int AW[12]  = {1, 2, 3, 1, 2, 3, 1, 2, 3, 1, 2, 3};
        const float rv0 = (h >= 1) ? 1.f : 0.f;
        const float rv2 = (h <= HH - 2) ? 1.f : 0.f;
        const float cv0 = (wj >= 1) ? 1.f : 0.f;
        const float cv2 = (wj <= WW - 2) ? 1.f : 0.f;
        float gm[3][3];
#pragma unroll
        for (int kw = 0; kw < 3; ++kw) {
            const float cv = (kw == 0) ? cv0 : (kw == 2) ? cv2 : 1.f;
            gm[0][kw] = g[0][kw] * rv0 * cv;
            gm[1][kw] = g[1][kw] * cv;
            gm[2][kw] = g[2][kw] * rv2 * cv;
        }
        float a = 0.f;
#pragma unroll
        for (int si = 0; si < 12; ++si) {
            const int sh = SHV[si], sw = SWV[si];
            float sum = 0.f;
#pragma unroll
            for (int kh = 0; kh < 3; ++kh)
#pragma unroll
                for (int kw = 0; kw < 3; ++kw) {
                    const int rr = (h + kh - 1 - sh) & (HH - 1);
                    int ccol = wj + kw - 1 - sw;
                    if (ccol < 0) ccol += WW;
                    if (ccol >= WW) ccol -= WW;
                    sum = fmaf(gm[kh][kw], sp[rr * WW + ccol], sum);
                }
            a = fmaf(wts[AW[si]], fmaxf(sum + rbb, 0.f), a);
        }
        const size_t base = (size_t)bc * HW + h * WW + wj;
        out[base] = x[base] + a;
    }
}

// ---------------------------------------------------------------------------
extern "C" void kernel_launch(void* const* d_in, const int* in_sizes, int n_in,
                              void* d_out, int out_size) {
    const float* x        = (const float*)d_in[0];
    const float* conv_w   = (const float*)d_in[1];
    const float* conv_b   = (const float*)d_in[2];
    const float* bn_gamma = (const float*)d_in[3];
    const float* bn_beta  = (const float*)d_in[4];
    const float* bn_mean  = (const float*)d_in[5];
    const float* bn_var   = (const float*)d_in[6];
    const float* refine_w = (const float*)d_in[7];
    const float* refine_b = (const float*)d_in[8];
    const float* rbn_gamma = (const float*)d_in[9];
    const float* rbn_beta  = (const float*)d_in[10];
    const float* rbn_mean  = (const float*)d_in[11];
    const float* rbn_var   = (const float*)d_in[12];
    float* out = (float*)d_out;

    const double s2 = 2.0 * 1.5 * 1.5;
    const double e1 = exp(-1.0 / s2), e2 = exp(-4.0 / s2), e3 = exp(-9.0 / s2);
    const double wsum = 4.0 * (e1 + e2 + e3);
    const float w1 = (float)(0.5 * e1 / wsum);
    const float w2 = (float)(0.5 * e2 / wsum);
    const float w3 = (float)(0.5 * e3 / wsum);

    cudaFuncSetAttribute(k_gemm, cudaFuncAttributeMaxDynamicSharedMemorySize,
                         GEMM_SMEM);
    cudaFuncSetAttribute(k_refine, cudaFuncAttributeMaxDynamicSharedMemorySize,
                         REFINE_SMEM);

    k_tw<<<CCH, CCH>>>(conv_w, conv_b, bn_gamma, bn_beta, bn_mean, bn_var);

    dim3 gg(HW / BN, BATCH);   // (160, 8)
    k_gemm<<<gg, 256, GEMM_SMEM>>>(x);

    k_refine<<<BATCH * CCH, 256, REFINE_SMEM>>>(x, refine_w, refine_b,
                                                rbn_gamma, rbn_beta, rbn_mean,
                                                rbn_var, out, w1, w2, w3);
}

// round 8
// speedup vs baseline: 2.3125x; 1.0080x over previous
#include <cuda_runtime.h>
#include <math.h>
#include <cstdint>

// Problem constants
#define BATCH 8
#define CCH   256
#define HH    64
#define WW    160
#define HW    (HH * WW)           // 10240
#define NTOT  (BATCH * CCH * HW)  // 20,971,520
#define NQ    (WW / 4)            // 40 quads per row
#define NG    (HH / 4)            // 16 row-groups of 4

// Scratch
__device__ float g_y[NTOT];          // y = relu(bn(1x1conv(x)))
__device__ float g_wt[CCH * CCH];    // tf32(s1[m] * W[m][k]) stored [k][m]
__device__ float g_b1[CCH];          // folded BN bias

// ---------------------------------------------------------------------------
__device__ __forceinline__ uint32_t smem_u32(const void* p) {
    uint32_t a;
    asm("{ .reg .u64 t; cvta.to.shared.u64 t, %1; cvt.u32.u64 %0, t; }"
        : "=r"(a) : "l"(p));
    return a;
}
__device__ __forceinline__ float tf32r(float x) {
    asm("cvt.rna.tf32.f32 %0, %1;" : "=f"(x) : "f"(x));
    return x;
}
__device__ __forceinline__ void cp16(uint32_t s, const void* g) {
    asm volatile("cp.async.cg.shared.global [%0], [%1], 16;" :: "r"(s), "l"(g));
}

// ---------------------------------------------------------------------------
// K0: fold BN into W: g_wt[k][m] = tf32(s1[m]*W[m][k]); g_b1[m]
// ---------------------------------------------------------------------------
__global__ void k_tw(const float* __restrict__ W, const float* __restrict__ conv_b,
                     const float* __restrict__ gamma, const float* __restrict__ beta,
                     const float* __restrict__ mean, const float* __restrict__ var) {
    const int m = blockIdx.x, k = threadIdx.x;
    const float s = gamma[m] * rsqrtf(var[m] + 1e-5f);
    g_wt[k * CCH + m] = tf32r(s * W[m * CCH + k]);
    if (k == 0) g_b1[m] = (conv_b[m] - mean[m]) * s + beta[m];
}

// ---------------------------------------------------------------------------
// K1: tf32 mma.sync GEMM + fused bias + ReLU
//   y[b][m][n] = relu( sum_k g_wt[k][m]*X[b][k][n] + b1[m] )
// Tile 256x128 (BM=256 all-M, BN=128), BK=32, 512 threads = 16 warps (4m x 4n),
// warp tile 64x32 = 4x4 frags m16n8k8. Both operands cp.async double-buffered;
// raw fp32 bits fed as tf32. One syncthreads per ktile. grid (80, 8).
// ---------------------------------------------------------------------------
#define BK   32
#define BN   128
#define APAD 264
#define BPAD 136
#define ASZ  (BK * APAD)
#define BSZ  (BK * BPAD)
#define GEMM_SMEM ((2 * ASZ + 2 * BSZ) * 4)   // 102400 B

__global__ __launch_bounds__(512, 1)
void k_gemm(const float* __restrict__ X) {
    extern __shared__ float smg[];
    float* As = smg;               // 2 buffers [BK][APAD]
    float* Bs = smg + 2 * ASZ;     // 2 buffers [BK][BPAD]
    const int tid = threadIdx.x;
    const int wid = tid >> 5, lane = tid & 31;
    const int n0 = blockIdx.x * BN;
    const int b  = blockIdx.y;
    const uint32_t smbA = smem_u32(As);
    const uint32_t smbB = smem_u32(Bs);
    const float* Xb = X + (size_t)b * CCH * HW;

    // ---- prologue: stage tile 0 ----
#pragma unroll
    for (int i = 0; i < 4; ++i) {
        const int idx = tid + i * 512;           // 0..2047
        const int row = idx >> 6, c4 = idx & 63;
        cp16(smbA + (row * APAD + c4 * 4) * 4, g_wt + row * CCH + c4 * 4);
    }
#pragma unroll
    for (int i = 0; i < 2; ++i) {
        const int idx = tid + i * 512;           // 0..1023
        const int row = idx >> 5, c4 = idx & 31;
        cp16(smbB + (row * BPAD + c4 * 4) * 4,
             Xb + (size_t)row * HW + n0 + c4 * 4);
    }
    asm volatile("cp.async.commit_group;" ::: "memory");

    float acc[4][4][4];
#pragma unroll
    for (int im = 0; im < 4; ++im)
#pragma unroll
        for (int in = 0; in < 4; ++in)
#pragma unroll
            for (int r = 0; r < 4; ++r) acc[im][in][r] = 0.f;

    const int mw = wid >> 2, nw = wid & 3;       // 4 x 4 warp grid
    const int lr = lane >> 2, lc = lane & 3;

    for (int kc = 0; kc < 8; ++kc) {
        const int bf = kc & 1;
        asm volatile("cp.async.wait_group 0;" ::: "memory");
        __syncthreads();   // loads visible + prev compute done (buffer reuse safe)

        if (kc < 7) {   // stage tile kc+1 into the other buffer
            const uint32_t dA = smbA + ((bf ^ 1) * ASZ) * 4;
            const uint32_t dB = smbB + ((bf ^ 1) * BSZ) * 4;
#pragma unroll
            for (int i = 0; i < 4; ++i) {
                const int idx = tid + i * 512;
                const int row = idx >> 6, c4 = idx & 63;
                cp16(dA + (row * APAD + c4 * 4) * 4,
                     g_wt + ((kc + 1) * BK + row) * CCH + c4 * 4);
            }
#pragma unroll
            for (int i = 0; i < 2; ++i) {
                const int idx = tid + i * 512;
                const int row = idx >> 5, c4 = idx & 31;
                cp16(dB + (row * BPAD + c4 * 4) * 4,
                     Xb + (size_t)((kc + 1) * BK + row) * HW + n0 + c4 * 4);
            }
            asm volatile("cp.async.commit_group;" ::: "memory");
        }

        const float* Ab  = As + bf * ASZ + lc * APAD + mw * 64 + lr;
        const float* Bbf = Bs + bf * BSZ + lc * BPAD + nw * 32 + lr;
#pragma unroll
        for (int ks = 0; ks < 4; ++ks) {
            const float* Ak = Ab + ks * 8 * APAD;
            const float* Bk = Bbf + ks * 8 * BPAD;
            uint32_t a[4][4], bb[4][2];
#pragma unroll
            for (int im = 0; im < 4; ++im) {
                a[im][0] = *(const uint32_t*)(Ak + im * 16);
                a[im][1] = *(const uint32_t*)(Ak + im * 16 + 8);
                a[im][2] = *(const uint32_t*)(Ak + im * 16 + 4 * APAD);
                a[im][3] = *(const uint32_t*)(Ak + im * 16 + 8 + 4 * APAD);
            }
#pragma unroll
            for (int in = 0; in < 4; ++in) {
                bb[in][0] = *(const uint32_t*)(Bk + in * 8);
                bb[in][1] = *(const uint32_t*)(Bk + in * 8 + 4 * BPAD);
            }
#pragma unroll
            for (int im = 0; im < 4; ++im)
#pragma unroll
                for (int in = 0; in < 4; ++in) {
                    asm volatile(
                        "mma.sync.aligned.m16n8k8.row.col.f32.tf32.tf32.f32 "
                        "{%0,%1,%2,%3}, {%4,%5,%6,%7}, {%8,%9}, {%0,%1,%2,%3};"
                        : "+f"(acc[im][in][0]), "+f"(acc[im][in][1]),
                          "+f"(acc[im][in][2]), "+f"(acc[im][in][3])
                        : "r"(a[im][0]), "r"(a[im][1]), "r"(a[im][2]), "r"(a[im][3]),
                          "r"(bb[in][0]), "r"(bb[in][1]));
                }
        }
        // no end-of-loop sync: top-of-next-iteration barrier covers buffer reuse
    }

    // epilogue: bias + ReLU -> g_y (acc is thread-private; no sync needed)
#pragma unroll
    for (int im = 0; im < 4; ++im) {
        const int r0 = mw * 64 + im * 16 + lr;
        const float bz0 = g_b1[r0], bz1 = g_b1[r0 + 8];
#pragma unroll
        for (int in = 0; in < 4; ++in) {
            const int nc = n0 + nw * 32 + in * 8 + lc * 2;
            float* p0 = g_y + ((size_t)(b * CCH + r0)) * HW + nc;
            float* p1 = p0 + (size_t)8 * HW;
            float2 v0, v1;
            v0.x = fmaxf(acc[im][in][0] + bz0, 0.f);
            v0.y = fmaxf(acc[im][in][1] + bz0, 0.f);
            v1.x = fmaxf(acc[im][in][2] + bz1, 0.f);
            v1.y = fmaxf(acc[im][in][3] + bz1, 0.f);
            *(float2*)p0 = v0;
            *(float2*)p1 = v1;
        }
    }
}

// ---------------------------------------------------------------------------
// K2: refine via circular-conv factorization, 4-row register blocking.
//   phase Z:   z = relu(circ_conv3x3(y) + rbb)   rolling 3-row window
//   phase ACC: out = x + Kv*z + Kh*z             10-row register column
//   phase BORDER: 444 true-border px, masked formula.
// ---------------------------------------------------------------------------
#define REFINE_SMEM (2 * HW * 4)

__device__ __forceinline__ void row_acc(float z[4], const float* gr,
                                        const float4& L, const float4& C,
                                        const float4& R) {
    const float w6[6] = {L.w, C.x, C.y, C.z, C.w, R.x};
#pragma unroll
    for (int j = 0; j < 4; ++j) {
        z[j] = fmaf(gr[0], w6[j],     z[j]);
        z[j] = fmaf(gr[1], w6[j + 1], z[j]);
        z[j] = fmaf(gr[2], w6[j + 2], z[j]);
    }
}

__global__ __launch_bounds__(256, 2)
void k_refine(const float* __restrict__ x,
              const float* __restrict__ rw, const float* __restrict__ rbias,
              const float* __restrict__ rg, const float* __restrict__ rbeta,
              const float* __restrict__ rmu, const float* __restrict__ rvar,
              float* __restrict__ out,
              float w1, float w2, float w3) {
    extern __shared__ float smr[];
    float* sp = smr;        // y plane
    float* zp = smr + HW;   // z plane
    const float4* sp4 = (const float4*)sp;
    float4* zp4 = (float4*)zp;

    const int bc = blockIdx.x;
    const int c  = bc & 255;
    const int tid = threadIdx.x;

    {
        const float4* yp4 = (const float4*)(g_y + (size_t)bc * HW);
        float4* d4 = (float4*)sp;
        for (int i = tid; i < HW / 4; i += 256) d4[i] = yp4[i];
    }
    const float rs  = rg[c] * rsqrtf(rvar[c] + 1e-5f);
    const float rbb = (rbias[c] - rmu[c]) * rs + rbeta[c];
    float g[3][3];
#pragma unroll
    for (int k = 0; k < 9; ++k) ((float*)g)[k] = rs * __ldg(rw + c * 9 + k);
    const float wts[4] = {0.f, w1, w2, w3};
    __syncthreads();

    // ---- phase Z: 4-row strips, rolling 3-row window ----
    for (int it = tid; it < NG * NQ; it += 256) {
        const int g4 = it / NQ;
        const int wq = it - g4 * NQ;
        const int h0 = g4 << 2;
        const int ql = wq ? wq - 1 : NQ - 1;
        const int qr = (wq == NQ - 1) ? 0 : wq + 1;

        float4 La, Ca, Ra, Lb, Cb, Rb;
        {
            const int rm = (h0 + HH - 1) & (HH - 1);
            La = sp4[rm * NQ + ql]; Ca = sp4[rm * NQ + wq]; Ra = sp4[rm * NQ + qr];
            Lb = sp4[h0 * NQ + ql]; Cb = sp4[h0 * NQ + wq]; Rb = sp4[h0 * NQ + qr];
        }
#pragma unroll
        for (int i = 0; i < 4; ++i) {
            const int rn = (h0 + i + 1) & (HH - 1);
            const float4 Lc = sp4[rn * NQ + ql];
            const float4 Cc = sp4[rn * NQ + wq];
            const float4 Rc = sp4[rn * NQ + qr];
            float z[4] = {rbb, rbb, rbb, rbb};
            row_acc(z, g[0], La, Ca, Ra);
            row_acc(z, g[1], Lb, Cb, Rb);
            row_acc(z, g[2], Lc, Cc, Rc);
            float4 zo;
            zo.x = fmaxf(z[0], 0.f); zo.y = fmaxf(z[1], 0.f);
            zo.z = fmaxf(z[2], 0.f); zo.w = fmaxf(z[3], 0.f);
            zp4[(h0 + i) * NQ + wq] = zo;
            La = Lb; Ca = Cb; Ra = Rb;
            Lb = Lc; Cb = Cc; Rb = Rc;
        }
    }
    __syncthreads();

    // ---- phase ACC: 4-row strips, 10-row vertical register column ----
    for (int it = tid; it < NG * NQ; it += 256) {
        const int g4 = it / NQ;
        const int wq = it - g4 * NQ;
        const int h0 = g4 << 2;
        const int ql = wq ? wq - 1 : NQ - 1;
        const int qr = (wq == NQ - 1) ? 0 : wq + 1;

        float4 zv[10];
#pragma unroll
        for (int j = 0; j < 10; ++j)
            zv[j] = zp4[((h0 - 3 + j) & (HH - 1)) * NQ + wq];

#pragma unroll
        for (int i = 0; i < 4; ++i) {
            float acc[4] = {0.f, 0.f, 0.f, 0.f};
#pragma unroll
            for (int s = 1; s <= 3; ++s) {
                const float wt = wts[s];
                const float4 u = zv[i + 3 - s];
                const float4 d = zv[i + 3 + s];
                acc[0] = fmaf(wt, u.x + d.x, acc[0]);
                acc[1] = fmaf(wt, u.y + d.y, acc[1]);
                acc[2] = fmaf(wt, u.z + d.z, acc[2]);
                acc[3] = fmaf(wt, u.w + d.w, acc[3]);
            }
            const int hh = h0 + i;
            float zr[12];
            *(float4*)(zr)     = zp4[hh * NQ + ql];
            *(float4*)(zr + 4) = zv[i + 3];
            *(float4*)(zr + 8) = zp4[hh * NQ + qr];
#pragma unroll
            for (int s = 1; s <= 3; ++s) {
                const float wt = wts[s];
#pragma unroll
                for (int j = 0; j < 4; ++j)
                    acc[j] = fmaf(wt, zr[4 + j - s] + zr[4 + j + s], acc[j]);
            }
            const size_t base = (size_t)bc * HW + hh * WW + wq * 4;
            const float4 xv = *(const float4*)(x + base);
            float4 o4;
            o4.x = xv.x + acc[0]; o4.y = xv.y + acc[1];
            o4.z = xv.z + acc[2]; o4.w = xv.w + acc[3];
            if (hh >= 1 && hh <= HH - 2 && wq >= 1 && wq <= NQ - 2) {
                *(float4*)(out + base) = o4;
            } else {
#pragma unroll
                for (int j = 0; j < 4; ++j) {
                    const int wj = wq * 4 + j;
                    if (hh >= 1 && hh <= HH - 2 && wj >= 1 && wj <= WW - 2)
                        out[base + j] = ((const float*)&o4)[j];
                }
            }
        }
    }

    // ---- phase BORDER: 444 true-border px, masked formula (validated) ----
    for (int i = tid; i < 2 * WW + 2 * (HH - 2); i += 256) {
        int h, wj;
        if (i < 2 * WW) { h = (i < WW) ? 0 : HH - 1; wj = (i < WW) ? i : i - WW; }
        else { const int j = i - 2 * WW; h = 1 + (j >> 1); wj = (j & 1) ? WW - 1 : 0; }

        const int SHV[12] = {1, 2, 3, -1, -2, -3, 0, 0, 0, 0, 0, 0};
        const int SWV[12] = {0, 0, 0, 0, 0, 0, -1, -2, -3, 1, 2, 3};
        const int AW[12]  = {1, 2, 3, 1, 2, 3, 1, 2, 3, 1, 2, 3};
        const float rv0 = (h >= 1) ? 1.f : 0.f;
        const float rv2 = (h <= HH - 2) ? 1.f : 0.f;
        const float cv0 = (wj >= 1) ? 1.f : 0.f;
        const float cv2 = (wj <= WW - 2) ? 1.f : 0.f;
        float gm[3][3];
#pragma unroll
        for (int kw = 0; kw < 3; ++kw) {
            const float cv = (kw == 0) ? cv0 : (kw == 2) ? cv2 : 1.f;
            gm[0][kw] = g[0][kw] * rv0 * cv;
            gm[1][kw] = g[1][kw] * cv;
            gm[2][kw] = g[2][kw] * rv2 * cv;
        }
        float a = 0.f;
#pragma unroll
        for (int si = 0; si < 12; ++si) {
            const int sh = SHV[si], sw = SWV[si];
            float sum = 0.f;
#pragma unroll
            for (int kh = 0; kh < 3; ++kh)
#pragma unroll
                for (int kw = 0; kw < 3; ++kw) {
                    const int rr = (h + kh - 1 - sh) & (HH - 1);
                    int ccol = wj + kw - 1 - sw;
                    if (ccol < 0) ccol += WW;
                    if (ccol >= WW) ccol -= WW;
                    sum = fmaf(gm[kh][kw], sp[rr * WW + ccol], sum);
                }
            a = fmaf(wts[AW[si]], fmaxf(sum + rbb, 0.f), a);
        }
        const size_t base = (size_t)bc * HW + h * WW + wj;
        out[base] = x[base] + a;
    }
}

// ---------------------------------------------------------------------------
extern "C" void kernel_launch(void* const* d_in, const int* in_sizes, int n_in,
                              void* d_out, int out_size) {
    const float* x        = (const float*)d_in[0];
    const float* conv_w   = (const float*)d_in[1];
    const float* conv_b   = (const float*)d_in[2];
    const float* bn_gamma = (const float*)d_in[3];
    const float* bn_beta  = (const float*)d_in[4];
    const float* bn_mean  = (const float*)d_in[5];
    const float* bn_var   = (const float*)d_in[6];
    const float* refine_w = (const float*)d_in[7];
    const float* refine_b = (const float*)d_in[8];
    const float* rbn_gamma = (const float*)d_in[9];
    const float* rbn_beta  = (const float*)d_in[10];
    const float* rbn_mean  = (const float*)d_in[11];
    const float* rbn_var   = (const float*)d_in[12];
    float* out = (float*)d_out;

    const double s2 = 2.0 * 1.5 * 1.5;
    const double e1 = exp(-1.0 / s2), e2 = exp(-4.0 / s2), e3 = exp(-9.0 / s2);
    const double wsum = 4.0 * (e1 + e2 + e3);
    const float w1 = (float)(0.5 * e1 / wsum);
    const float w2 = (float)(0.5 * e2 / wsum);
    const float w3 = (float)(0.5 * e3 / wsum);

    cudaFuncSetAttribute(k_gemm, cudaFuncAttributeMaxDynamicSharedMemorySize,
                         GEMM_SMEM);
    cudaFuncSetAttribute(k_refine, cudaFuncAttributeMaxDynamicSharedMemorySize,
                         REFINE_SMEM);

    k_tw<<<CCH, CCH>>>(conv_w, conv_b, bn_gamma, bn_beta, bn_mean, bn_var);

    dim3 gg(HW / BN, BATCH);   // (80, 8)
    k_gemm<<<gg, 512, GEMM_SMEM>>>(x);

    k_refine<<<BATCH * CCH, 256, REFINE_SMEM>>>(x, refine_w, refine_b,
                                                rbn_gamma, rbn_beta, rbn_mean,
                                                rbn_var, out, w1, w2, w3);
}

// round 9
// speedup vs baseline: 2.5809x; 1.1160x over previous
#include <cuda_runtime.h>
#include <cuda_fp16.h>
#include <math.h>
#include <cstdint>

// Problem constants
#define BATCH 8
#define CCH   256
#define HH    64
#define WW    160
#define HW    (HH * WW)           // 10240
#define NTOT  (BATCH * CCH * HW)  // 20,971,520
#define NQ    (WW / 4)            // 40 quads per row
#define NG    (HH / 4)            // 16 row-groups of 4

// Scratch
__device__ float  g_y[NTOT];          // y = relu(bn(1x1conv(x)))
__device__ __half g_wh[CCH * CCH];    // fp16(s1[m] * W[m][k]), [m][k]
__device__ float  g_b1[CCH];          // folded BN bias

// ---------------------------------------------------------------------------
__device__ __forceinline__ uint32_t smem_u32(const void* p) {
    uint32_t a;
    asm("{ .reg .u64 t; cvta.to.shared.u64 t, %1; cvt.u32.u64 %0, t; }"
        : "=r"(a) : "l"(p));
    return a;
}
__device__ __forceinline__ void cp16(uint32_t s, const void* g) {
    asm volatile("cp.async.cg.shared.global [%0], [%1], 16;" :: "r"(s), "l"(g));
}

__global__ void k_nop() {}   // ncu alignment: shifts -s 5 capture onto k_gemm

// ---------------------------------------------------------------------------
// K0: fold BN into W (fp16): g_wh[m][k] = fp16(s1[m]*W[m][k]); g_b1[m]
// ---------------------------------------------------------------------------
__global__ void k_tw(const float* __restrict__ W, const float* __restrict__ conv_b,
                     const float* __restrict__ gamma, const float* __restrict__ beta,
                     const float* __restrict__ mean, const float* __restrict__ var) {
    const int m = blockIdx.x, k = threadIdx.x;
    const float s = gamma[m] * rsqrtf(var[m] + 1e-5f);
    g_wh[m * CCH + k] = __float2half_rn(s * W[m * CCH + k]);
    if (k == 0) g_b1[m] = (conv_b[m] - mean[m]) * s + beta[m];
}

// ---------------------------------------------------------------------------
// K1: fp16 mma.sync m16n8k16 GEMM + fused bias + ReLU
//   y[b][m][n] = relu( sum_k Wh[m][k]*X[b][k][n] + b1[m] )
// Tile 256x128, BK=32, 512 threads = 16 warps (4m x 4n), warp tile 64x32.
// A (fp16) via cp.async double-buffer, frags via LDS.32 (conflict-free).
// B: LDG fp32 -> cvt fp16 -> STS into other buffer; frags via ldmatrix.x2.trans.
// Half the HMMA instruction count of the tf32 k8 version. grid (80, 8).
// ---------------------------------------------------------------------------
#define BK      32
#define BN      128
#define APITCH  40                 // halfs; banks (20m+lc)%32 distinct
#define BPITCH  136                // halfs; ldmatrix rows stride 272B -> banks 4r
#define ASZ     (256 * APITCH)     // halfs per buffer
#define BSZ     (BK * BPITCH)
#define GEMM_SMEM ((2 * ASZ + 2 * BSZ) * 2)   // 58368 B

__global__ __launch_bounds__(512, 1)
void k_gemm(const float* __restrict__ X) {
    extern __shared__ __half smh[];
    __half* As = smh;                // 2 buffers [256][APITCH]
    __half* Bs = smh + 2 * ASZ;      // 2 buffers [BK][BPITCH]
    const int tid = threadIdx.x;
    const int wid = tid >> 5, lane = tid & 31;
    const int n0 = blockIdx.x * BN;
    const int b  = blockIdx.y;
    const uint32_t smbA = smem_u32(As);
    const uint32_t smbB = smem_u32(Bs);
    const float* Xb = X + (size_t)b * CCH * HW;

    const int mw = wid >> 2, nw = wid & 3;       // 4 x 4 warp grid
    const int lr = lane >> 2, lc = lane & 3;

    // ---- prologue: A tile 0 (cp.async), B tile 0 (LDG+cvt+STS) ----
#pragma unroll
    for (int i = 0; i < 2; ++i) {
        const int idx = tid + i * 512;           // 0..1023
        const int row = idx >> 2, c8 = idx & 3;  // 4 x 16B chunks per 32-half row
        cp16(smbA + (row * APITCH + c8 * 8) * 2, g_wh + row * CCH + c8 * 8);
    }
    asm volatile("cp.async.commit_group;" ::: "memory");
#pragma unroll
    for (int i = 0; i < 2; ++i) {
        const int idx = tid + i * 512;
        const int row = idx >> 5, c4 = idx & 31;
        const float4 v = *(const float4*)(Xb + (size_t)row * HW + n0 + c4 * 4);
        __half2 h0 = __floats2half2_rn(v.x, v.y);
        __half2 h1 = __floats2half2_rn(v.z, v.w);
        *(__half2*)(Bs + row * BPITCH + c4 * 4)     = h0;
        *(__half2*)(Bs + row * BPITCH + c4 * 4 + 2) = h1;
    }

    float acc[4][4][4];
#pragma unroll
    for (int im = 0; im < 4; ++im)
#pragma unroll
        for (int in = 0; in < 4; ++in)
#pragma unroll
            for (int r = 0; r < 4; ++r) acc[im][in][r] = 0.f;

    for (int kc = 0; kc < 8; ++kc) {
        const int bf = kc & 1;
        asm volatile("cp.async.wait_group 0;" ::: "memory");
        __syncthreads();

        float4 bv[2];
        if (kc < 7) {   // stage tile kc+1 into the other buffer
            const uint32_t dA = smbA + ((bf ^ 1) * ASZ) * 2;
#pragma unroll
            for (int i = 0; i < 2; ++i) {
                const int idx = tid + i * 512;
                const int row = idx >> 2, c8 = idx & 3;
                cp16(dA + (row * APITCH + c8 * 8) * 2,
                     g_wh + row * CCH + (kc + 1) * BK + c8 * 8);
            }
            asm volatile("cp.async.commit_group;" ::: "memory");
#pragma unroll
            for (int i = 0; i < 2; ++i) {
                const int idx = tid + i * 512;
                const int row = idx >> 5, c4 = idx & 31;
                bv[i] = *(const float4*)(Xb + (size_t)((kc + 1) * BK + row) * HW
                                         + n0 + c4 * 4);
            }
        }

        // ---- compute: 2 x k16 steps, 16 mma each ----
        const __half* Ab = As + bf * ASZ;
        const uint32_t bB = smbB + (bf * BSZ) * 2;
#pragma unroll
        for (int ks = 0; ks < 2; ++ks) {
            uint32_t a[4][4], bfr[4][2];
#pragma unroll
            for (int im = 0; im < 4; ++im) {
                const int m = mw * 64 + im * 16 + lr;
                const __half* ap = Ab + m * APITCH + ks * 16 + lc * 2;
                a[im][0] = *(const uint32_t*)(ap);
                a[im][1] = *(const uint32_t*)(ap + 8 * APITCH);
                a[im][2] = *(const uint32_t*)(ap + 8);
                a[im][3] = *(const uint32_t*)(ap + 8 * APITCH + 8);
            }
#pragma unroll
            for (int in = 0; in < 4; ++in) {
                const uint32_t addr = bB +
                    ((ks * 16 + (lane & 15)) * BPITCH + nw * 32 + in * 8) * 2;
                asm volatile(
                    "ldmatrix.sync.aligned.m8n8.x2.trans.shared.b16 {%0,%1}, [%2];"
                    : "=r"(bfr[in][0]), "=r"(bfr[in][1]) : "r"(addr));
            }
#pragma unroll
            for (int im = 0; im < 4; ++im)
#pragma unroll
                for (int in = 0; in < 4; ++in) {
                    asm volatile(
                        "mma.sync.aligned.m16n8k16.row.col.f32.f16.f16.f32 "
                        "{%0,%1,%2,%3}, {%4,%5,%6,%7}, {%8,%9}, {%0,%1,%2,%3};"
                        : "+f"(acc[im][in][0]), "+f"(acc[im][in][1]),
                          "+f"(acc[im][in][2]), "+f"(acc[im][in][3])
                        : "r"(a[im][0]), "r"(a[im][1]), "r"(a[im][2]), "r"(a[im][3]),
                          "r"(bfr[in][0]), "r"(bfr[in][1]));
                }
        }

        if (kc < 7) {   // cvt + store staged B into other buffer
            __half* Bd = Bs + (bf ^ 1) * BSZ;
#pragma unroll
            for (int i = 0; i < 2; ++i) {
                const int idx = tid + i * 512;
                const int row = idx >> 5, c4 = idx & 31;
                __half2 h0 = __floats2half2_rn(bv[i].x, bv[i].y);
                __half2 h1 = __floats2half2_rn(bv[i].z, bv[i].w);
                *(__half2*)(Bd + row * BPITCH + c4 * 4)     = h0;
                *(__half2*)(Bd + row * BPITCH + c4 * 4 + 2) = h1;
            }
        }
        // next iteration's top-of-loop syncthreads orders STS/cp.async vs reads
    }

    // ---- epilogue: bias + ReLU -> g_y ----
#pragma unroll
    for (int im = 0; im < 4; ++im) {
        const int r0 = mw * 64 + im * 16 + lr;
        const float bz0 = g_b1[r0], bz1 = g_b1[r0 + 8];
#pragma unroll
        for (int in = 0; in < 4; ++in) {
            const int nc = n0 + nw * 32 + in * 8 + lc * 2;
            float* p0 = g_y + ((size_t)(b * CCH + r0)) * HW + nc;
            float* p1 = p0 + (size_t)8 * HW;
            float2 v0, v1;
            v0.x = fmaxf(acc[im][in][0] + bz0, 0.f);
            v0.y = fmaxf(acc[im][in][1] + bz0, 0.f);
            v1.x = fmaxf(acc[im][in][2] + bz1, 0.f);
            v1.y = fmaxf(acc[im][in][3] + bz1, 0.f);
            *(float2*)p0 = v0;
            *(float2*)p1 = v1;
        }
    }
}

// ---------------------------------------------------------------------------
// K2: refine via circular-conv factorization, 4-row register blocking.
// (unchanged from R7 — validated)
// ---------------------------------------------------------------------------
#define REFINE_SMEM (2 * HW * 4)

__device__ __forceinline__ void row_acc(float z[4], const float* gr,
                                        const float4& L, const float4& C,
                                        const float4& R) {
    const float w6[6] = {L.w, C.x, C.y, C.z, C.w, R.x};
#pragma unroll
    for (int j = 0; j < 4; ++j) {
        z[j] = fmaf(gr[0], w6[j],     z[j]);
        z[j] = fmaf(gr[1], w6[j + 1], z[j]);
        z[j] = fmaf(gr[2], w6[j + 2], z[j]);
    }
}

__global__ __launch_bounds__(256, 2)
void k_refine(const float* __restrict__ x,
              const float* __restrict__ rw, const float* __restrict__ rbias,
              const float* __restrict__ rg, const float* __restrict__ rbeta,
              const float* __restrict__ rmu, const float* __restrict__ rvar,
              float* __restrict__ out,
              float w1, float w2, float w3) {
    extern __shared__ float smr[];
    float* sp = smr;        // y plane
    float* zp = smr + HW;   // z plane
    const float4* sp4 = (const float4*)sp;
    float4* zp4 = (float4*)zp;

    const int bc = blockIdx.x;
    const int c  = bc & 255;
    const int tid = threadIdx.x;

    {
        const float4* yp4 = (const float4*)(g_y + (size_t)bc * HW);
        float4* d4 = (float4*)sp;
        for (int i = tid; i < HW / 4; i += 256) d4[i] = yp4[i];
    }
    const float rs  = rg[c] * rsqrtf(rvar[c] + 1e-5f);
    const float rbb = (rbias[c] - rmu[c]) * rs + rbeta[c];
    float g[3][3];
#pragma unroll
    for (int k = 0; k < 9; ++k) ((float*)g)[k] = rs * __ldg(rw + c * 9 + k);
    const float wts[4] = {0.f, w1, w2, w3};
    __syncthreads();

    // ---- phase Z ----
    for (int it = tid; it < NG * NQ; it += 256) {
        const int g4 = it / NQ;
        const int wq = it - g4 * NQ;
        const int h0 = g4 << 2;
        const int ql = wq ? wq - 1 : NQ - 1;
        const int qr = (wq == NQ - 1) ? 0 : wq + 1;

        float4 La, Ca, Ra, Lb, Cb, Rb;
        {
            const int rm = (h0 + HH - 1) & (HH - 1);
            La = sp4[rm * NQ + ql]; Ca = sp4[rm * NQ + wq]; Ra = sp4[rm * NQ + qr];
            Lb = sp4[h0 * NQ + ql]; Cb = sp4[h0 * NQ + wq]; Rb = sp4[h0 * NQ + qr];
        }
#pragma unroll
        for (int i = 0; i < 4; ++i) {
            const int rn = (h0 + i + 1) & (HH - 1);
            const float4 Lc = sp4[rn * NQ + ql];
            const float4 Cc = sp4[rn * NQ + wq];
            const float4 Rc = sp4[rn * NQ + qr];
            float z[4] = {rbb, rbb, rbb, rbb};
            row_acc(z, g[0], La, Ca, Ra);
            row_acc(z, g[1], Lb, Cb, Rb);
            row_acc(z, g[2], Lc, Cc, Rc);
            float4 zo;
            zo.x = fmaxf(z[0], 0.f); zo.y = fmaxf(z[1], 0.f);
            zo.z = fmaxf(z[2], 0.f); zo.w = fmaxf(z[3], 0.f);
            zp4[(h0 + i) * NQ + wq] = zo;
            La = Lb; Ca = Cb; Ra = Rb;
            Lb = Lc; Cb = Cc; Rb = Rc;
        }
    }
    __syncthreads();

    // ---- phase ACC ----
    for (int it = tid; it < NG * NQ; it += 256) {
        const int g4 = it / NQ;
        const int wq = it - g4 * NQ;
        const int h0 = g4 << 2;
        const int ql = wq ? wq - 1 : NQ - 1;
        const int qr = (wq == NQ - 1) ? 0 : wq + 1;

        float4 zv[10];
#pragma unroll
        for (int j = 0; j < 10; ++j)
            zv[j] = zp4[((h0 - 3 + j) & (HH - 1)) * NQ + wq];

#pragma unroll
        for (int i = 0; i < 4; ++i) {
            float acc[4] = {0.f, 0.f, 0.f, 0.f};
#pragma unroll
            for (int s = 1; s <= 3; ++s) {
                const float wt = wts[s];
                const float4 u = zv[i + 3 - s];
                const float4 d = zv[i + 3 + s];
                acc[0] = fmaf(wt, u.x + d.x, acc[0]);
                acc[1] = fmaf(wt, u.y + d.y, acc[1]);
                acc[2] = fmaf(wt, u.z + d.z, acc[2]);
                acc[3] = fmaf(wt, u.w + d.w, acc[3]);
            }
            const int hh = h0 + i;
            float zr[12];
            *(float4*)(zr)     = zp4[hh * NQ + ql];
            *(float4*)(zr + 4) = zv[i + 3];
            *(float4*)(zr + 8) = zp4[hh * NQ + qr];
#pragma unroll
            for (int s = 1; s <= 3; ++s) {
                const float wt = wts[s];
#pragma unroll
                for (int j = 0; j < 4; ++j)
                    acc[j] = fmaf(wt, zr[4 + j - s] + zr[4 + j + s], acc[j]);
            }
            const size_t base = (size_t)bc * HW + hh * WW + wq * 4;
            const float4 xv = *(const float4*)(x + base);
            float4 o4;
            o4.x = xv.x + acc[0]; o4.y = xv.y + acc[1];
            o4.z = xv.z + acc[2]; o4.w = xv.w + acc[3];
            if (hh >= 1 && hh <= HH - 2 && wq >= 1 && wq <= NQ - 2) {
                *(float4*)(out + base) = o4;
            } else {
#pragma unroll
                for (int j = 0; j < 4; ++j) {
                    const int wj = wq * 4 + j;
                    if (hh >= 1 && hh <= HH - 2 && wj >= 1 && wj <= WW - 2)
                        out[base + j] = ((const float*)&o4)[j];
                }
            }
        }
    }

    // ---- phase BORDER ----
    for (int i = tid; i < 2 * WW + 2 * (HH - 2); i += 256) {
        int h, wj;
        if (i < 2 * WW) { h = (i < WW) ? 0 : HH - 1; wj = (i < WW) ? i : i - WW; }
        else { const int j = i - 2 * WW; h = 1 + (j >> 1); wj = (j & 1) ? WW - 1 : 0; }

        const int SHV[12] = {1, 2, 3, -1, -2, -3, 0, 0, 0, 0, 0, 0};
        const int SWV[12] = {0, 0, 0, 0, 0, 0, -1, -2, -3, 1, 2, 3};
        const int AW[12]  = {1, 2, 3, 1, 2, 3, 1, 2, 3, 1, 2, 3};
        const float rv0 = (h >= 1) ? 1.f : 0.f;
        const float rv2 = (h <= HH - 2) ? 1.f : 0.f;
        const float cv0 = (wj >= 1) ? 1.f : 0.f;
        const float cv2 = (wj <= WW - 2) ? 1.f : 0.f;
        float gm[3][3];
#pragma unroll
        for (int kw = 0; kw < 3; ++kw) {
            const float cv = (kw == 0) ? cv0 : (kw == 2) ? cv2 : 1.f;
            gm[0][kw] = g[0][kw] * rv0 * cv;
            gm[1][kw] = g[1][kw] * cv;
            gm[2][kw] = g[2][kw] * rv2 * cv;
        }
        float a = 0.f;
#pragma unroll
        for (int si = 0; si < 12; ++si) {
            const int sh = SHV[si], sw = SWV[si];
            float sum = 0.f;
#pragma unroll
            for (int kh = 0; kh < 3; ++kh)
#pragma unroll
                for (int kw = 0; kw < 3; ++kw) {
                    const int rr = (h + kh - 1 - sh) & (HH - 1);
                    int ccol = wj + kw - 1 - sw;
                    if (ccol < 0) ccol += WW;
                    if (ccol >= WW) ccol -= WW;
                    sum = fmaf(gm[kh][kw], sp[rr * WW + ccol], sum);
                }
            a = fmaf(wts[AW[si]], fmaxf(sum + rbb, 0.f), a);
        }
        const size_t base = (size_t)bc * HW + h * WW + wj;
        out[base] = x[base] + a;
    }
}

// ---------------------------------------------------------------------------
extern "C" void kernel_launch(void* const* d_in, const int* in_sizes, int n_in,
                              void* d_out, int out_size) {
    const float* x        = (const float*)d_in[0];
    const float* conv_w   = (const float*)d_in[1];
    const float* conv_b   = (const float*)d_in[2];
    const float* bn_gamma = (const float*)d_in[3];
    const float* bn_beta  = (const float*)d_in[4];
    const float* bn_mean  = (const float*)d_in[5];
    const float* bn_var   = (const float*)d_in[6];
    const float* refine_w = (const float*)d_in[7];
    const float* refine_b = (const float*)d_in[8];
    const float* rbn_gamma = (const float*)d_in[9];
    const float* rbn_beta  = (const float*)d_in[10];
    const float* rbn_mean  = (const float*)d_in[11];
    const float* rbn_var   = (const float*)d_in[12];
    float* out = (float*)d_out;

    const double s2 = 2.0 * 1.5 * 1.5;
    const double e1 = exp(-1.0 / s2), e2 = exp(-4.0 / s2), e3 = exp(-9.0 / s2);
    const double wsum = 4.0 * (e1 + e2 + e3);
    const float w1 = (float)(0.5 * e1 / wsum);
    const float w2 = (float)(0.5 * e2 / wsum);
    const float w3 = (float)(0.5 * e3 / wsum);

    cudaFuncSetAttribute(k_gemm, cudaFuncAttributeMaxDynamicSharedMemorySize,
                         GEMM_SMEM);
    cudaFuncSetAttribute(k_refine, cudaFuncAttributeMaxDynamicSharedMemorySize,
                         REFINE_SMEM);

    // two no-op launches shift ncu's -s 5 capture onto k_gemm
    k_nop<<<1, 32>>>();
    k_nop<<<1, 32>>>();

    k_tw<<<CCH, CCH>>>(conv_w, conv_b, bn_gamma, bn_beta, bn_mean, bn_var);

    dim3 gg(HW / BN, BATCH);   // (80, 8)
    k_gemm<<<gg, 512, GEMM_SMEM>>>(x);

    k_refine<<<BATCH * CCH, 256, REFINE_SMEM>>>(x, refine_w, refine_b,
                                                rbn_gamma, rbn_beta, rbn_mean,
                                                rbn_var, out, w1, w2, w3);
}

// round 10
// speedup vs baseline: 3.1655x; 1.2265x over previous
#include <cuda_runtime.h>
#include <cuda_fp16.h>
#include <math.h>
#include <cstdint>

// Problem constants
#define BATCH 8
#define CCH   256
#define HH    64
#define WW    160
#define HW    (HH * WW)           // 10240
#define NTOT  (BATCH * CCH * HW)  // 20,971,520
#define NQ    (WW / 4)            // 40 quads per row
#define NG    (HH / 4)            // 16 row-groups of 4

// Scratch
__device__ float  g_y[NTOT];          // y = relu(bn(1x1conv(x)))
__device__ __half g_wh[CCH * CCH];    // fp16(s1[m] * W[m][k]), [m][k]
__device__ float  g_b1[CCH];          // folded BN bias

// ---------------------------------------------------------------------------
__device__ __forceinline__ uint32_t smem_u32(const void* p) {
    uint32_t a;
    asm("{ .reg .u64 t; cvta.to.shared.u64 t, %1; cvt.u32.u64 %0, t; }"
        : "=r"(a) : "l"(p));
    return a;
}
__device__ __forceinline__ void cp16(uint32_t s, const void* g) {
    asm volatile("cp.async.cg.shared.global [%0], [%1], 16;" :: "r"(s), "l"(g));
}

__global__ void k_nop() {}   // launch-order shim: puts k_refine at capture idx 3

// ---------------------------------------------------------------------------
// K0: fold BN into W (fp16): g_wh[m][k] = fp16(s1[m]*W[m][k]); g_b1[m]
// ---------------------------------------------------------------------------
__global__ void k_tw(const float* __restrict__ W, const float* __restrict__ conv_b,
                     const float* __restrict__ gamma, const float* __restrict__ beta,
                     const float* __restrict__ mean, const float* __restrict__ var) {
    const int m = blockIdx.x, k = threadIdx.x;
    const float s = gamma[m] * rsqrtf(var[m] + 1e-5f);
    g_wh[m * CCH + k] = __float2half_rn(s * W[m * CCH + k]);
    if (k == 0) g_b1[m] = (conv_b[m] - mean[m]) * s + beta[m];
}

// ---------------------------------------------------------------------------
// K1: fp16 mma.sync m16n8k16 GEMM + fused bias + ReLU  (unchanged from R8)
// ---------------------------------------------------------------------------
#define BK      32
#define BN      128
#define APITCH  40
#define BPITCH  136
#define ASZ     (256 * APITCH)
#define BSZ     (BK * BPITCH)
#define GEMM_SMEM ((2 * ASZ + 2 * BSZ) * 2)   // 58368 B

__global__ __launch_bounds__(512, 1)
void k_gemm(const float* __restrict__ X) {
    extern __shared__ __half smh[];
    __half* As = smh;                // 2 buffers [256][APITCH]
    __half* Bs = smh + 2 * ASZ;      // 2 buffers [BK][BPITCH]
    const int tid = threadIdx.x;
    const int wid = tid >> 5, lane = tid & 31;
    const int n0 = blockIdx.x * BN;
    const int b  = blockIdx.y;
    const uint32_t smbA = smem_u32(As);
    const uint32_t smbB = smem_u32(Bs);
    const float* Xb = X + (size_t)b * CCH * HW;

    const int mw = wid >> 2, nw = wid & 3;
    const int lr = lane >> 2, lc = lane & 3;

#pragma unroll
    for (int i = 0; i < 2; ++i) {
        const int idx = tid + i * 512;
        const int row = idx >> 2, c8 = idx & 3;
        cp16(smbA + (row * APITCH + c8 * 8) * 2, g_wh + row * CCH + c8 * 8);
    }
    asm volatile("cp.async.commit_group;" ::: "memory");
#pragma unroll
    for (int i = 0; i < 2; ++i) {
        const int idx = tid + i * 512;
        const int row = idx >> 5, c4 = idx & 31;
        const float4 v = *(const float4*)(Xb + (size_t)row * HW + n0 + c4 * 4);
        __half2 h0 = __floats2half2_rn(v.x, v.y);
        __half2 h1 = __floats2half2_rn(v.z, v.w);
        *(__half2*)(Bs + row * BPITCH + c4 * 4)     = h0;
        *(__half2*)(Bs + row * BPITCH + c4 * 4 + 2) = h1;
    }

    float acc[4][4][4];
#pragma unroll
    for (int im = 0; im < 4; ++im)
#pragma unroll
        for (int in = 0; in < 4; ++in)
#pragma unroll
            for (int r = 0; r < 4; ++r) acc[im][in][r] = 0.f;

    for (int kc = 0; kc < 8; ++kc) {
        const int bf = kc & 1;
        asm volatile("cp.async.wait_group 0;" ::: "memory");
        __syncthreads();

        float4 bv[2];
        if (kc < 7) {
            const uint32_t dA = smbA + ((bf ^ 1) * ASZ) * 2;
#pragma unroll
            for (int i = 0; i < 2; ++i) {
                const int idx = tid + i * 512;
                const int row = idx >> 2, c8 = idx & 3;
                cp16(dA + (row * APITCH + c8 * 8) * 2,
                     g_wh + row * CCH + (kc + 1) * BK + c8 * 8);
            }
            asm volatile("cp.async.commit_group;" ::: "memory");
#pragma unroll
            for (int i = 0; i < 2; ++i) {
                const int idx = tid + i * 512;
                const int row = idx >> 5, c4 = idx & 31;
                bv[i] = *(const float4*)(Xb + (size_t)((kc + 1) * BK + row) * HW
                                         + n0 + c4 * 4);
            }
        }

        const __half* Ab = As + bf * ASZ;
        const uint32_t bB = smbB + (bf * BSZ) * 2;
#pragma unroll
        for (int ks = 0; ks < 2; ++ks) {
            uint32_t a[4][4], bfr[4][2];
#pragma unroll
            for (int im = 0; im < 4; ++im) {
                const int m = mw * 64 + im * 16 + lr;
                const __half* ap = Ab + m * APITCH + ks * 16 + lc * 2;
                a[im][0] = *(const uint32_t*)(ap);
                a[im][1] = *(const uint32_t*)(ap + 8 * APITCH);
                a[im][2] = *(const uint32_t*)(ap + 8);
                a[im][3] = *(const uint32_t*)(ap + 8 * APITCH + 8);
            }
#pragma unroll
            for (int in = 0; in < 4; ++in) {
                const uint32_t addr = bB +
                    ((ks * 16 + (lane & 15)) * BPITCH + nw * 32 + in * 8) * 2;
                asm volatile(
                    "ldmatrix.sync.aligned.m8n8.x2.trans.shared.b16 {%0,%1}, [%2];"
                    : "=r"(bfr[in][0]), "=r"(bfr[in][1]) : "r"(addr));
            }
#pragma unroll
            for (int im = 0; im < 4; ++im)
#pragma unroll
                for (int in = 0; in < 4; ++in) {
                    asm volatile(
                        "mma.sync.aligned.m16n8k16.row.col.f32.f16.f16.f32 "
                        "{%0,%1,%2,%3}, {%4,%5,%6,%7}, {%8,%9}, {%0,%1,%2,%3};"
                        : "+f"(acc[im][in][0]), "+f"(acc[im][in][1]),
                          "+f"(acc[im][in][2]), "+f"(acc[im][in][3])
                        : "r"(a[im][0]), "r"(a[im][1]), "r"(a[im][2]), "r"(a[im][3]),
                          "r"(bfr[in][0]), "r"(bfr[in][1]));
                }
        }

        if (kc < 7) {
            __half* Bd = Bs + (bf ^ 1) * BSZ;
#pragma unroll
            for (int i = 0; i < 2; ++i) {
                const int idx = tid + i * 512;
                const int row = idx >> 5, c4 = idx & 31;
                __half2 h0 = __floats2half2_rn(bv[i].x, bv[i].y);
                __half2 h1 = __floats2half2_rn(bv[i].z, bv[i].w);
                *(__half2*)(Bd + row * BPITCH + c4 * 4)     = h0;
                *(__half2*)(Bd + row * BPITCH + c4 * 4 + 2) = h1;
            }
        }
    }

#pragma unroll
    for (int im = 0; im < 4; ++im) {
        const int r0 = mw * 64 + im * 16 + lr;
        const float bz0 = g_b1[r0], bz1 = g_b1[r0 + 8];
#pragma unroll
        for (int in = 0; in < 4; ++in) {
            const int nc = n0 + nw * 32 + in * 8 + lc * 2;
            float* p0 = g_y + ((size_t)(b * CCH + r0)) * HW + nc;
            float* p1 = p0 + (size_t)8 * HW;
            float2 v0, v1;
            v0.x = fmaxf(acc[im][in][0] + bz0, 0.f);
            v0.y = fmaxf(acc[im][in][1] + bz0, 0.f);
            v1.x = fmaxf(acc[im][in][2] + bz1, 0.f);
            v1.y = fmaxf(acc[im][in][3] + bz1, 0.f);
            *(float2*)p0 = v0;
            *(float2*)p1 = v1;
        }
    }
}

// ---------------------------------------------------------------------------
// K2: refine, no y-staging version.
//   phase Z: z = relu(circ_conv3x3(y)+rbb) reading y straight from GMEM
//            (rolling 3-row window; plane stays L2-resident; smem holds z only)
//   phase ACC: out = x + Kv*z + Kh*z from smem z (10-row register column)
//   phase BORDER: 444 px masked formula, y from GMEM.
// smem 40 KB -> 3 CTAs/SM (24 warps, was 16).
// ---------------------------------------------------------------------------
#define REFINE_SMEM (HW * 4)

__device__ __forceinline__ void row_acc(float z[4], const float* gr,
                                        const float4& L, const float4& C,
                                        const float4& R) {
    const float w6[6] = {L.w, C.x, C.y, C.z, C.w, R.x};
#pragma unroll
    for (int j = 0; j < 4; ++j) {
        z[j] = fmaf(gr[0], w6[j],     z[j]);
        z[j] = fmaf(gr[1], w6[j + 1], z[j]);
        z[j] = fmaf(gr[2], w6[j + 2], z[j]);
    }
}

__global__ __launch_bounds__(256, 3)
void k_refine(const float* __restrict__ x,
              const float* __restrict__ rw, const float* __restrict__ rbias,
              const float* __restrict__ rg, const float* __restrict__ rbeta,
              const float* __restrict__ rmu, const float* __restrict__ rvar,
              float* __restrict__ out,
              float w1, float w2, float w3) {
    extern __shared__ float zp[];            // z plane only, 40 KB
    float4* zp4 = (float4*)zp;

    const int bc = blockIdx.x;
    const int c  = bc & 255;
    const int tid = threadIdx.x;
    const float* __restrict__ ypl = g_y + (size_t)bc * HW;
    const float4* __restrict__ yp4 = (const float4*)ypl;

    const float rs  = rg[c] * rsqrtf(rvar[c] + 1e-5f);
    const float rbb = (rbias[c] - rmu[c]) * rs + rbeta[c];
    float g[3][3];
#pragma unroll
    for (int k = 0; k < 9; ++k) ((float*)g)[k] = rs * __ldg(rw + c * 9 + k);
    const float wts[4] = {0.f, w1, w2, w3};

    // ---- phase Z: 4-row strips, rolling 3-row window, y from GMEM ----
    for (int it = tid; it < NG * NQ; it += 256) {
        const int g4 = it / NQ;
        const int wq = it - g4 * NQ;
        const int h0 = g4 << 2;
        const int ql = wq ? wq - 1 : NQ - 1;
        const int qr = (wq == NQ - 1) ? 0 : wq + 1;

        float4 La, Ca, Ra, Lb, Cb, Rb;
        {
            const int rm = (h0 + HH - 1) & (HH - 1);
            La = yp4[rm * NQ + ql]; Ca = yp4[rm * NQ + wq]; Ra = yp4[rm * NQ + qr];
            Lb = yp4[h0 * NQ + ql]; Cb = yp4[h0 * NQ + wq]; Rb = yp4[h0 * NQ + qr];
        }
#pragma unroll
        for (int i = 0; i < 4; ++i) {
            const int rn = (h0 + i + 1) & (HH - 1);
            const float4 Lc = yp4[rn * NQ + ql];
            const float4 Cc = yp4[rn * NQ + wq];
            const float4 Rc = yp4[rn * NQ + qr];
            float z[4] = {rbb, rbb, rbb, rbb};
            row_acc(z, g[0], La, Ca, Ra);
            row_acc(z, g[1], Lb, Cb, Rb);
            row_acc(z, g[2], Lc, Cc, Rc);
            float4 zo;
            zo.x = fmaxf(z[0], 0.f); zo.y = fmaxf(z[1], 0.f);
            zo.z = fmaxf(z[2], 0.f); zo.w = fmaxf(z[3], 0.f);
            zp4[(h0 + i) * NQ + wq] = zo;
            La = Lb; Ca = Cb; Ra = Rb;
            Lb = Lc; Cb = Cc; Rb = Rc;
        }
    }
    __syncthreads();

    // ---- phase ACC: 4-row strips, 10-row vertical register column ----
    for (int it = tid; it < NG * NQ; it += 256) {
        const int g4 = it / NQ;
        const int wq = it - g4 * NQ;
        const int h0 = g4 << 2;
        const int ql = wq ? wq - 1 : NQ - 1;
        const int qr = (wq == NQ - 1) ? 0 : wq + 1;

        float4 zv[10];
#pragma unroll
        for (int j = 0; j < 10; ++j)
            zv[j] = zp4[((h0 - 3 + j) & (HH - 1)) * NQ + wq];

#pragma unroll
        for (int i = 0; i < 4; ++i) {
            float acc[4] = {0.f, 0.f, 0.f, 0.f};
#pragma unroll
            for (int s = 1; s <= 3; ++s) {
                const float wt = wts[s];
                const float4 u = zv[i + 3 - s];
                const float4 d = zv[i + 3 + s];
                acc[0] = fmaf(wt, u.x + d.x, acc[0]);
                acc[1] = fmaf(wt, u.y + d.y, acc[1]);
                acc[2] = fmaf(wt, u.z + d.z, acc[2]);
                acc[3] = fmaf(wt, u.w + d.w, acc[3]);
            }
            const int hh = h0 + i;
            float zr[12];
            *(float4*)(zr)     = zp4[hh * NQ + ql];
            *(float4*)(zr + 4) = zv[i + 3];
            *(float4*)(zr + 8) = zp4[hh * NQ + qr];
#pragma unroll
            for (int s = 1; s <= 3; ++s) {
                const float wt = wts[s];
#pragma unroll
                for (int j = 0; j < 4; ++j)
                    acc[j] = fmaf(wt, zr[4 + j - s] + zr[4 + j + s], acc[j]);
            }
            const size_t base = (size_t)bc * HW + hh * WW + wq * 4;
            const float4 xv = *(const float4*)(x + base);
            float4 o4;
            o4.x = xv.x + acc[0]; o4.y = xv.y + acc[1];
            o4.z = xv.z + acc[2]; o4.w = xv.w + acc[3];
            if (hh >= 1 && hh <= HH - 2 && wq >= 1 && wq <= NQ - 2) {
                *(float4*)(out + base) = o4;
            } else {
#pragma unroll
                for (int j = 0; j < 4; ++j) {
                    const int wj = wq * 4 + j;
                    if (hh >= 1 && hh <= HH - 2 && wj >= 1 && wj <= WW - 2)
                        out[base + j] = ((const float*)&o4)[j];
                }
            }
        }
    }

    // ---- phase BORDER: 444 true-border px, masked formula, y from GMEM ----
    for (int i = tid; i < 2 * WW + 2 * (HH - 2); i += 256) {
        int h, wj;
        if (i < 2 * WW) { h = (i < WW) ? 0 : HH - 1; wj = (i < WW) ? i : i - WW; }
        else { const int j = i - 2 * WW; h = 1 + (j >> 1); wj = (j & 1) ? WW - 1 : 0; }

        const int SHV[12] = {1, 2, 3, -1, -2, -3, 0, 0, 0, 0, 0, 0};
        const int SWV[12] = {0, 0, 0, 0, 0, 0, -1, -2, -3, 1, 2, 3};
        const int AW[12]  = {1, 2, 3, 1, 2, 3, 1, 2, 3, 1, 2, 3};
        const float rv0 = (h >= 1) ? 1.f : 0.f;
        const float rv2 = (h <= HH - 2) ? 1.f : 0.f;
        const float cv0 = (wj >= 1) ? 1.f : 0.f;
        const float cv2 = (wj <= WW - 2) ? 1.f : 0.f;
        float gm[3][3];
#pragma unroll
        for (int kw = 0; kw < 3; ++kw) {
            const float cv = (kw == 0) ? cv0 : (kw == 2) ? cv2 : 1.f;
            gm[0][kw] = g[0][kw] * rv0 * cv;
            gm[1][kw] = g[1][kw] * cv;
            gm[2][kw] = g[2][kw] * rv2 * cv;
        }
        float a = 0.f;
#pragma unroll
        for (int si = 0; si < 12; ++si) {
            const int sh = SHV[si], sw = SWV[si];
            float sum = 0.f;
#pragma unroll
            for (int kh = 0; kh < 3; ++kh)
#pragma unroll
                for (int kw = 0; kw < 3; ++kw) {
                    const int rr = (h + kh - 1 - sh) & (HH - 1);
                    int ccol = wj + kw - 1 - sw;
                    if (ccol < 0) ccol += WW;
                    if (ccol >= WW) ccol -= WW;
                    sum = fmaf(gm[kh][kw], ypl[rr * WW + ccol], sum);
                }
            a = fmaf(wts[AW[si]], fmaxf(sum + rbb, 0.f), a);
        }
        const size_t base = (size_t)bc * HW + h * WW + wj;
        out[base] = x[base] + a;
    }
}

// ---------------------------------------------------------------------------
extern "C" void kernel_launch(void* const* d_in, const int* in_sizes, int n_in,
                              void* d_out, int out_size) {
    const float* x        = (const float*)d_in[0];
    const float* conv_w   = (const float*)d_in[1];
    const float* conv_b   = (const float*)d_in[2];
    const float* bn_gamma = (const float*)d_in[3];
    const float* bn_beta  = (const float*)d_in[4];
    const float* bn_mean  = (const float*)d_in[5];
    const float* bn_var   = (const float*)d_in[6];
    const float* refine_w = (const float*)d_in[7];
    const float* refine_b = (const float*)d_in[8];
    const float* rbn_gamma = (const float*)d_in[9];
    const float* rbn_beta  = (const float*)d_in[10];
    const float* rbn_mean  = (const float*)d_in[11];
    const float* rbn_var   = (const float*)d_in[12];
    float* out = (float*)d_out;

    const double s2 = 2.0 * 1.5 * 1.5;
    const double e1 = exp(-1.0 / s2), e2 = exp(-4.0 / s2), e3 = exp(-9.0 / s2);
    const double wsum = 4.0 * (e1 + e2 + e3);
    const float w1 = (float)(0.5 * e1 / wsum);
    const float w2 = (float)(0.5 * e2 / wsum);
    const float w3 = (float)(0.5 * e3 / wsum);

    cudaFuncSetAttribute(k_gemm, cudaFuncAttributeMaxDynamicSharedMemorySize,
                         GEMM_SMEM);
    cudaFuncSetAttribute(k_refine, cudaFuncAttributeMaxDynamicSharedMemorySize,
                         REFINE_SMEM);

    // order: capture index 3 (empirical) lands on k_refine this round
    k_nop<<<1, 32>>>();

    k_tw<<<CCH, CCH>>>(conv_w, conv_b, bn_gamma, bn_beta, bn_mean, bn_var);

    dim3 gg(HW / BN, BATCH);   // (80, 8)
    k_gemm<<<gg, 512, GEMM_SMEM>>>(x);

    k_refine<<<BATCH * CCH, 256, REFINE_SMEM>>>(x, refine_w, refine_b,
                                                rbn_gamma, rbn_beta, rbn_mean,
                                                rbn_var, out, w1, w2, w3);
}

// round 12
// speedup vs baseline: 3.4611x; 1.0934x over previous
#include <cuda_runtime.h>
#include <cuda_fp16.h>
#include <math.h>
#include <cstdint>

// Problem constants
#define BATCH 8
#define CCH   256
#define HH    64
#define WW    160
#define HW    (HH * WW)           // 10240
#define NTOT  (BATCH * CCH * HW)  // 20,971,520
#define NQ    (WW / 4)            // 40 quads per row
#define NG    (HH / 4)            // 16 row-groups of 4

// Scratch
__device__ __half g_yh[NTOT];         // y = relu(bn(1x1conv(x))), fp16
__device__ __half g_wh[CCH * CCH];    // fp16(s1[m] * W[m][k]), [m][k]
__device__ float  g_b1[CCH];          // folded BN bias

// ---------------------------------------------------------------------------
__device__ __forceinline__ uint32_t smem_u32(const void* p) {
    uint32_t a;
    asm("{ .reg .u64 t; cvta.to.shared.u64 t, %1; cvt.u32.u64 %0, t; }"
        : "=r"(a) : "l"(p));
    return a;
}
__device__ __forceinline__ void cp16(uint32_t s, const void* g) {
    asm volatile("cp.async.cg.shared.global [%0], [%1], 16;" :: "r"(s), "l"(g));
}
// 4 packed halfs -> float4
__device__ __forceinline__ float4 h4f(uint2 u) {
    const float2 a = __half22float2(*(const __half2*)&u.x);
    const float2 b = __half22float2(*(const __half2*)&u.y);
    return make_float4(a.x, a.y, b.x, b.y);
}

__global__ void k_nop() {}   // launch-order shim: capture idx 3 -> k_refine

// ---------------------------------------------------------------------------
// K0: fold BN into W (fp16): g_wh[m][k] = fp16(s1[m]*W[m][k]); g_b1[m]
// ---------------------------------------------------------------------------
__global__ void k_tw(const float* __restrict__ W, const float* __restrict__ conv_b,
                     const float* __restrict__ gamma, const float* __restrict__ beta,
                     const float* __restrict__ mean, const float* __restrict__ var) {
    const int m = blockIdx.x, k = threadIdx.x;
    const float s = gamma[m] * rsqrtf(var[m] + 1e-5f);
    g_wh[m * CCH + k] = __float2half_rn(s * W[m * CCH + k]);
    if (k == 0) g_b1[m] = (conv_b[m] - mean[m]) * s + beta[m];
}

// ---------------------------------------------------------------------------
// K1: fp16 mma.sync m16n8k16 GEMM + fused bias + ReLU -> fp16 y
// (inner loop identical to R9/R10 winner; epilogue now writes __half2)
// ---------------------------------------------------------------------------
#define BK      32
#define BN      128
#define APITCH  40
#define BPITCH  136
#define ASZ     (256 * APITCH)
#define BSZ     (BK * BPITCH)
#define GEMM_SMEM ((2 * ASZ + 2 * BSZ) * 2)   // 58368 B

__global__ __launch_bounds__(512, 1)
void k_gemm(const float* __restrict__ X) {
    extern __shared__ __half smh[];
    __half* As = smh;                // 2 buffers [256][APITCH]
    __half* Bs = smh + 2 * ASZ;      // 2 buffers [BK][BPITCH]
    const int tid = threadIdx.x;
    const int wid = tid >> 5, lane = tid & 31;
    const int n0 = blockIdx.x * BN;
    const int b  = blockIdx.y;
    const uint32_t smbA = smem_u32(As);
    const uint32_t smbB = smem_u32(Bs);
    const float* Xb = X + (size_t)b * CCH * HW;

    const int mw = wid >> 2, nw = wid & 3;
    const int lr = lane >> 2, lc = lane & 3;

#pragma unroll
    for (int i = 0; i < 2; ++i) {
        const int idx = tid + i * 512;
        const int row = idx >> 2, c8 = idx & 3;
        cp16(smbA + (row * APITCH + c8 * 8) * 2, g_wh + row * CCH + c8 * 8);
    }
    asm volatile("cp.async.commit_group;" ::: "memory");
#pragma unroll
    for (int i = 0; i < 2; ++i) {
        const int idx = tid + i * 512;
        const int row = idx >> 5, c4 = idx & 31;
        const float4 v = *(const float4*)(Xb + (size_t)row * HW + n0 + c4 * 4);
        __half2 h0 = __floats2half2_rn(v.x, v.y);
        __half2 h1 = __floats2half2_rn(v.z, v.w);
        *(__half2*)(Bs + row * BPITCH + c4 * 4)     = h0;
        *(__half2*)(Bs + row * BPITCH + c4 * 4 + 2) = h1;
    }

    float acc[4][4][4];
#pragma unroll
    for (int im = 0; im < 4; ++im)
#pragma unroll
        for (int in = 0; in < 4; ++in)
#pragma unroll
            for (int r = 0; r < 4; ++r) acc[im][in][r] = 0.f;

    for (int kc = 0; kc < 8; ++kc) {
        const int bf = kc & 1;
        asm volatile("cp.async.wait_group 0;" ::: "memory");
        __syncthreads();

        float4 bv[2];
        if (kc < 7) {
            const uint32_t dA = smbA + ((bf ^ 1) * ASZ) * 2;
#pragma unroll
            for (int i = 0; i < 2; ++i) {
                const int idx = tid + i * 512;
                const int row = idx >> 2, c8 = idx & 3;
                cp16(dA + (row * APITCH + c8 * 8) * 2,
                     g_wh + row * CCH + (kc + 1) * BK + c8 * 8);
            }
            asm volatile("cp.async.commit_group;" ::: "memory");
#pragma unroll
            for (int i = 0; i < 2; ++i) {
                const int idx = tid + i * 512;
                const int row = idx >> 5, c4 = idx & 31;
                bv[i] = *(const float4*)(Xb + (size_t)((kc + 1) * BK + row) * HW
                                         + n0 + c4 * 4);
            }
        }

        const __half* Ab = As + bf * ASZ;
        const uint32_t bB = smbB + (bf * BSZ) * 2;
#pragma unroll
        for (int ks = 0; ks < 2; ++ks) {
            uint32_t a[4][4], bfr[4][2];
#pragma unroll
            for (int im = 0; im < 4; ++im) {
                const int m = mw * 64 + im * 16 + lr;
                const __half* ap = Ab + m * APITCH + ks * 16 + lc * 2;
                a[im][0] = *(const uint32_t*)(ap);
                a[im][1] = *(const uint32_t*)(ap + 8 * APITCH);
                a[im][2] = *(const uint32_t*)(ap + 8);
                a[im][3] = *(const uint32_t*)(ap + 8 * APITCH + 8);
            }
#pragma unroll
            for (int in = 0; in < 4; ++in) {
                const uint32_t addr = bB +
                    ((ks * 16 + (lane & 15)) * BPITCH + nw * 32 + in * 8) * 2;
                asm volatile(
                    "ldmatrix.sync.aligned.m8n8.x2.trans.shared.b16 {%0,%1}, [%2];"
                    : "=r"(bfr[in][0]), "=r"(bfr[in][1]) : "r"(addr));
            }
#pragma unroll
            for (int im = 0; im < 4; ++im)
#pragma unroll
                for (int in = 0; in < 4; ++in) {
                    asm volatile(
                        "mma.sync.aligned.m16n8k16.row.col.f32.f16.f16.f32 "
                        "{%0,%1,%2,%3}, {%4,%5,%6,%7}, {%8,%9}, {%0,%1,%2,%3};"
                        : "+f"(acc[im][in][0]), "+f"(acc[im][in][1]),
                          "+f"(acc[im][in][2]), "+f"(acc[im][in][3])
                        : "r"(a[im][0]), "r"(a[im][1]), "r"(a[im][2]), "r"(a[im][3]),
                          "r"(bfr[in][0]), "r"(bfr[in][1]));
                }
        }

        if (kc < 7) {
            __half* Bd = Bs + (bf ^ 1) * BSZ;
#pragma unroll
            for (int i = 0; i < 2; ++i) {
                const int idx = tid + i * 512;
                const int row = idx >> 5, c4 = idx & 31;
                __half2 h0 = __floats2half2_rn(bv[i].x, bv[i].y);
                __half2 h1 = __floats2half2_rn(bv[i].z, bv[i].w);
                *(__half2*)(Bd + row * BPITCH + c4 * 4)     = h0;
                *(__half2*)(Bd + row * BPITCH + c4 * 4 + 2) = h1;
            }
        }
    }

    // epilogue: bias + ReLU -> fp16 y
#pragma unroll
    for (int im = 0; im < 4; ++im) {
        const int r0 = mw * 64 + im * 16 + lr;
        const float bz0 = g_b1[r0], bz1 = g_b1[r0 + 8];
#pragma unroll
        for (int in = 0; in < 4; ++in) {
            const int nc = n0 + nw * 32 + in * 8 + lc * 2;
            __half* p0 = g_yh + ((size_t)(b * CCH + r0)) * HW + nc;
            __half* p1 = p0 + (size_t)8 * HW;
            *(__half2*)p0 = __floats2half2_rn(fmaxf(acc[im][in][0] + bz0, 0.f),
                                              fmaxf(acc[im][in][1] + bz0, 0.f));
            *(__half2*)p1 = __floats2half2_rn(fmaxf(acc[im][in][2] + bz1, 0.f),
                                              fmaxf(acc[im][in][3] + bz1, 0.f));
        }
    }
}

// ---------------------------------------------------------------------------
// K2: refine; y read as fp16 quads (uint2, 8B) -> halved L1 bytes.
// Structure identical to R10 winner.
// ---------------------------------------------------------------------------
#define REFINE_SMEM (HW * 4)

__device__ __forceinline__ void row_acc(float z[4], const float* gr,
                                        const float4& L, const float4& C,
                                        const float4& R) {
    const float w6[6] = {L.w, C.x, C.y, C.z, C.w, R.x};
#pragma unroll
    for (int j = 0; j < 4; ++j) {
        z[j] = fmaf(gr[0], w6[j],     z[j]);
        z[j] = fmaf(gr[1], w6[j + 1], z[j]);
        z[j] = fmaf(gr[2], w6[j + 2], z[j]);
    }
}

__global__ __launch_bounds__(256, 3)
void k_refine(const float* __restrict__ x,
              const float* __restrict__ rw, const float* __restrict__ rbias,
              const float* __restrict__ rg, const float* __restrict__ rbeta,
              const float* __restrict__ rmu, const float* __restrict__ rvar,
              float* __restrict__ out,
              float w1, float w2, float w3) {
    extern __shared__ float zp[];            // z plane, 40 KB (fp32)
    float4* zp4 = (float4*)zp;

    const int bc = blockIdx.x;
    const int c  = bc & 255;
    const int tid = threadIdx.x;
    const __half* __restrict__ ypl = g_yh + (size_t)bc * HW;
    const uint2* __restrict__ yq  = (const uint2*)ypl;   // 4-half quads

    const float rs  = rg[c] * rsqrtf(rvar[c] + 1e-5f);
    const float rbb = (rbias[c] - rmu[c]) * rs + rbeta[c];
    float g[3][3];
#pragma unroll
    for (int k = 0; k < 9; ++k) ((float*)g)[k] = rs * __ldg(rw + c * 9 + k);
    const float wts[4] = {0.f, w1, w2, w3};

    // ---- phase Z: 4-row strips, rolling 3-row window, y(fp16) from GMEM ----
    for (int it = tid; it < NG * NQ; it += 256) {
        const int g4 = it / NQ;
        const int wq = it - g4 * NQ;
        const int h0 = g4 << 2;
        const int ql = wq ? wq - 1 : NQ - 1;
        const int qr = (wq == NQ - 1) ? 0 : wq + 1;

        float4 La, Ca, Ra, Lb, Cb, Rb;
        {
            const int rm = (h0 + HH - 1) & (HH - 1);
            La = h4f(yq[rm * NQ + ql]); Ca = h4f(yq[rm * NQ + wq]); Ra = h4f(yq[rm * NQ + qr]);
            Lb = h4f(yq[h0 * NQ + ql]); Cb = h4f(yq[h0 * NQ + wq]); Rb = h4f(yq[h0 * NQ + qr]);
        }
#pragma unroll
        for (int i = 0; i < 4; ++i) {
            const int rn = (h0 + i + 1) & (HH - 1);
            const float4 Lc = h4f(yq[rn * NQ + ql]);
            const float4 Cc = h4f(yq[rn * NQ + wq]);
            const float4 Rc = h4f(yq[rn * NQ + qr]);
            float z[4] = {rbb, rbb, rbb, rbb};
            row_acc(z, g[0], La, Ca, Ra);
            row_acc(z, g[1], Lb, Cb, Rb);
            row_acc(z, g[2], Lc, Cc, Rc);
            float4 zo;
            zo.x = fmaxf(z[0], 0.f); zo.y = fmaxf(z[1], 0.f);
            zo.z = fmaxf(z[2], 0.f); zo.w = fmaxf(z[3], 0.f);
            zp4[(h0 + i) * NQ + wq] = zo;
            La = Lb; Ca = Cb; Ra = Rb;
            Lb = Lc; Cb = Cc; Rb = Rc;
        }
    }
    __syncthreads();

    // ---- phase ACC: 4-row strips, 10-row vertical register column ----
    for (int it = tid; it < NG * NQ; it += 256) {
        const int g4 = it / NQ;
        const int wq = it - g4 * NQ;
        const int h0 = g4 << 2;
        const int ql = wq ? wq - 1 : NQ - 1;
        const int qr = (wq == NQ - 1) ? 0 : wq + 1;

        float4 zv[10];
#pragma unroll
        for (int j = 0; j < 10; ++j)
            zv[j] = zp4[((h0 - 3 + j) & (HH - 1)) * NQ + wq];

#pragma unroll
        for (int i = 0; i < 4; ++i) {
            float acc[4] = {0.f, 0.f, 0.f, 0.f};
#pragma unroll
            for (int s = 1; s <= 3; ++s) {
                const float wt = wts[s];
                const float4 u = zv[i + 3 - s];
                const float4 d = zv[i + 3 + s];
                acc[0] = fmaf(wt, u.x + d.x, acc[0]);
                acc[1] = fmaf(wt, u.y + d.y, acc[1]);
                acc[2] = fmaf(wt, u.z + d.z, acc[2]);
                acc[3] = fmaf(wt, u.w + d.w, acc[3]);
            }
            const int hh = h0 + i;
            float zr[12];
            *(float4*)(zr)     = zp4[hh * NQ + ql];
            *(float4*)(zr + 4) = zv[i + 3];
            *(float4*)(zr + 8) = zp4[hh * NQ + qr];
#pragma unroll
            for (int s = 1; s <= 3; ++s) {
                const float wt = wts[s];
#pragma unroll
                for (int j = 0; j < 4; ++j)
                    acc[j] = fmaf(wt, zr[4 + j - s] + zr[4 + j + s], acc[j]);
            }
            const size_t base = (size_t)bc * HW + hh * WW + wq * 4;
            const float4 xv = *(const float4*)(x + base);
            float4 o4;
            o4.x = xv.x + acc[0]; o4.y = xv.y + acc[1];
            o4.z = xv.z + acc[2]; o4.w = xv.w + acc[3];
            if (hh >= 1 && hh <= HH - 2 && wq >= 1 && wq <= NQ - 2) {
                *(float4*)(out + base) = o4;
            } else {
#pragma unroll
                for (int j = 0; j < 4; ++j) {
                    const int wj = wq * 4 + j;
                    if (hh >= 1 && hh <= HH - 2 && wj >= 1 && wj <= WW - 2)
                        out[base + j] = ((const float*)&o4)[j];
                }
            }
        }
    }

    // ---- phase BORDER: 444 true-border px, masked formula, y(fp16) ----
    for (int i = tid; i < 2 * WW + 2 * (HH - 2); i += 256) {
        int h, wj;
        if (i < 2 * WW) { h = (i < WW) ? 0 : HH - 1; wj = (i < WW) ? i : i - WW; }
        else { const int j = i - 2 * WW; h = 1 + (j >> 1); wj = (j & 1) ? WW - 1 : 0; }

        const int SHV[12] = {1, 2, 3, -1, -2, -3, 0, 0, 0, 0, 0, 0};
        const int SWV[12] = {0, 0, 0, 0, 0, 0, -1, -2, -3, 1, 2, 3};
        const int AW[12]  = {1, 2, 3, 1, 2, 3, 1, 2, 3, 1, 2, 3};
        const float rv0 = (h >= 1) ? 1.f : 0.f;
        const float rv2 = (h <= HH - 2) ? 1.f : 0.f;
        const float cv0 = (wj >= 1) ? 1.f : 0.f;
        const float cv2 = (wj <= WW - 2) ? 1.f : 0.f;
        float gm[3][3];
#pragma unroll
        for (int kw = 0; kw < 3; ++kw) {
            const float cv = (kw == 0) ? cv0 : (kw == 2) ? cv2 : 1.f;
            gm[0][kw] = g[0][kw] * rv0 * cv;
            gm[1][kw] = g[1][kw] * cv;
            gm[2][kw] = g[2][kw] * rv2 * cv;
        }
        float a = 0.f;
#pragma unroll
        for (int si = 0; si < 12; ++si) {
            const int sh = SHV[si], sw = SWV[si];
            float sum = 0.f;
#pragma unroll
            for (int kh = 0; kh < 3; ++kh)
#pragma unroll
                for (int kw = 0; kw < 3; ++kw) {
                    const int rr = (h + kh - 1 - sh) & (HH - 1);
                    int ccol = wj + kw - 1 - sw;
                    if (ccol < 0) ccol += WW;
                    if (ccol >= WW) ccol -= WW;
                    sum = fmaf(gm[kh][kw], __half2float(ypl[rr * WW + ccol]), sum);
                }
            a = fmaf(wts[AW[si]], fmaxf(sum + rbb, 0.f), a);
        }
        const size_t base = (size_t)bc * HW + h * WW + wj;
        out[base] = x[base] + a;
    }
}

// ---------------------------------------------------------------------------
extern "C" void kernel_launch(void* const* d_in, const int* in_sizes, int n_in,
                              void* d_out, int out_size) {
    const float* x        = (const float*)d_in[0];
    const float* conv_w   = (const float*)d_in[1];
    const float* conv_b   = (const float*)d_in[2];
    const float* bn_gamma = (const float*)d_in[3];
    const float* bn_beta  = (const float*)d_in[4];
    const float* bn_mean  = (const float*)d_in[5];
    const float* bn_var   = (const float*)d_in[6];
    const float* refine_w = (const float*)d_in[7];
    const float* refine_b = (const float*)d_in[8];
    const float* rbn_gamma = (const float*)d_in[9];
    const float* rbn_beta  = (const float*)d_in[10];
    const float* rbn_mean  = (const float*)d_in[11];
    const float* rbn_var   = (const float*)d_in[12];
    float* out = (float*)d_out;

    const double s2 = 2.0 * 1.5 * 1.5;
    const double e1 = exp(-1.0 / s2), e2 = exp(-4.0 / s2), e3 = exp(-9.0 / s2);
    const double wsum = 4.0 * (e1 + e2 + e3);
    const float w1 = (float)(0.5 * e1 / wsum);
    const float w2 = (float)(0.5 * e2 / wsum);
    const float w3 = (float)(0.5 * e3 / wsum);

    cudaFuncSetAttribute(k_gemm, cudaFuncAttributeMaxDynamicSharedMemorySize,
                         GEMM_SMEM);
    cudaFuncSetAttribute(k_refine, cudaFuncAttributeMaxDynamicSharedMemorySize,
                         REFINE_SMEM);

    // order: capture index 3 lands on k_refine (verify L1-byte prediction)
    k_nop<<<1, 32>>>();

    k_tw<<<CCH, CCH>>>(conv_w, conv_b, bn_gamma, bn_beta, bn_mean, bn_var);

    dim3 gg(HW / BN, BATCH);   // (80, 8)
    k_gemm<<<gg, 512, GEMM_SMEM>>>(x);

    k_refine<<<BATCH * CCH, 256, REFINE_SMEM>>>(x, refine_w, refine_b,
                                                rbn_gamma, rbn_beta, rbn_mean,
                                                rbn_var, out, w1, w2, w3);
}

// round 13
// speedup vs baseline: 3.7208x; 1.0750x over previous
#include <cuda_runtime.h>
#include <cuda_fp16.h>
#include <math.h>
#include <cstdint>

// Problem constants
#define BATCH 8
#define CCH   256
#define HH    64
#define WW    160
#define HW    (HH * WW)           // 10240
#define NTOT  (BATCH * CCH * HW)  // 20,971,520
#define NQ    (WW / 4)            // 40 quads per row
#define NG    (HH / 4)            // 16 row-groups of 4

// Scratch
__device__ __half g_yh[NTOT];         // y = relu(bn(1x1conv(x))), fp16
__device__ __half g_wh[CCH * CCH];    // fp16(s1[m] * W[m][k]), [m][k]
__device__ float  g_b1[CCH];          // folded BN bias

// ---------------------------------------------------------------------------
__device__ __forceinline__ uint32_t smem_u32(const void* p) {
    uint32_t a;
    asm("{ .reg .u64 t; cvta.to.shared.u64 t, %1; cvt.u32.u64 %0, t; }"
        : "=r"(a) : "l"(p));
    return a;
}
__device__ __forceinline__ void cp16(uint32_t s, const void* g) {
    asm volatile("cp.async.cg.shared.global [%0], [%1], 16;" :: "r"(s), "l"(g));
}
// 4 packed halfs -> float4
__device__ __forceinline__ float4 h4f(uint2 u) {
    const float2 a = __half22float2(*(const __half2*)&u.x);
    const float2 b = __half22float2(*(const __half2*)&u.y);
    return make_float4(a.x, a.y, b.x, b.y);
}

__global__ void k_nop() {}   // launch-order shims: capture idx 3 -> k_gemm

// ---------------------------------------------------------------------------
// K0: fold BN into W (fp16): g_wh[m][k] = fp16(s1[m]*W[m][k]); g_b1[m]
// ---------------------------------------------------------------------------
__global__ void k_tw(const float* __restrict__ W, const float* __restrict__ conv_b,
                     const float* __restrict__ gamma, const float* __restrict__ beta,
                     const float* __restrict__ mean, const float* __restrict__ var) {
    const int m = blockIdx.x, k = threadIdx.x;
    const float s = gamma[m] * rsqrtf(var[m] + 1e-5f);
    g_wh[m * CCH + k] = __float2half_rn(s * W[m * CCH + k]);
    if (k == 0) g_b1[m] = (conv_b[m] - mean[m]) * s + beta[m];
}

// ---------------------------------------------------------------------------
// K1: fp16 mma.sync m16n8k16 GEMM + fused bias + ReLU -> fp16 y
// Tile 128x128, BK=32, 256 threads = 8 warps (2m x 4n), warp tile 64x32.
// 2 CTAs/SM (barrier overlap). grid (80, 2, 8).
// ---------------------------------------------------------------------------
#define BM      128
#define BK      32
#define BN      128
#define APITCH  40
#define BPITCH  136
#define ASZ     (BM * APITCH)
#define BSZ     (BK * BPITCH)
#define GEMM_SMEM ((2 * ASZ + 2 * BSZ) * 2)   // 37888 B

__global__ __launch_bounds__(256, 2)
void k_gemm(const float* __restrict__ X) {
    extern __shared__ __half smh[];
    __half* As = smh;                // 2 buffers [BM][APITCH]
    __half* Bs = smh + 2 * ASZ;      // 2 buffers [BK][BPITCH]
    const int tid = threadIdx.x;
    const int wid = tid >> 5, lane = tid & 31;
    const int n0 = blockIdx.x * BN;
    const int m0 = blockIdx.y * BM;
    const int b  = blockIdx.z;
    const uint32_t smbA = smem_u32(As);
    const uint32_t smbB = smem_u32(Bs);
    const float* Xb = X + (size_t)b * CCH * HW;

    const int mw = wid >> 2, nw = wid & 3;       // 2m x 4n warp grid
    const int lr = lane >> 2, lc = lane & 3;

    // ---- prologue: A tile 0 (cp.async), B tile 0 (LDG+cvt+STS) ----
#pragma unroll
    for (int i = 0; i < 2; ++i) {
        const int idx = tid + i * 256;           // 0..511
        const int row = idx >> 2, c8 = idx & 3;  // 4 x 16B chunks per 32-half row
        cp16(smbA + (row * APITCH + c8 * 8) * 2,
             g_wh + (size_t)(m0 + row) * CCH + c8 * 8);
    }
    asm volatile("cp.async.commit_group;" ::: "memory");
#pragma unroll
    for (int i = 0; i < 4; ++i) {
        const int idx = tid + i * 256;           // 0..1023
        const int row = idx >> 5, c4 = idx & 31;
        const float4 v = *(const float4*)(Xb + (size_t)row * HW + n0 + c4 * 4);
        *(__half2*)(Bs + row * BPITCH + c4 * 4)     = __floats2half2_rn(v.x, v.y);
        *(__half2*)(Bs + row * BPITCH + c4 * 4 + 2) = __floats2half2_rn(v.z, v.w);
    }

    float acc[4][4][4];
#pragma unroll
    for (int im = 0; im < 4; ++im)
#pragma unroll
        for (int in = 0; in < 4; ++in)
#pragma unroll
            for (int r = 0; r < 4; ++r) acc[im][in][r] = 0.f;

    for (int kc = 0; kc < 8; ++kc) {
        const int bf = kc & 1;
        asm volatile("cp.async.wait_group 0;" ::: "memory");
        __syncthreads();

        float4 bv[4];
        if (kc < 7) {
            const uint32_t dA = smbA + ((bf ^ 1) * ASZ) * 2;
#pragma unroll
            for (int i = 0; i < 2; ++i) {
                const int idx = tid + i * 256;
                const int row = idx >> 2, c8 = idx & 3;
                cp16(dA + (row * APITCH + c8 * 8) * 2,
                     g_wh + (size_t)(m0 + row) * CCH + (kc + 1) * BK + c8 * 8);
            }
            asm volatile("cp.async.commit_group;" ::: "memory");
#pragma unroll
            for (int i = 0; i < 4; ++i) {
                const int idx = tid + i * 256;
                const int row = idx >> 5, c4 = idx & 31;
                bv[i] = *(const float4*)(Xb + (size_t)((kc + 1) * BK + row) * HW
                                         + n0 + c4 * 4);
            }
        }

        const __half* Ab = As + bf * ASZ;
        const uint32_t bB = smbB + (bf * BSZ) * 2;
#pragma unroll
        for (int ks = 0; ks < 2; ++ks) {
            uint32_t a[4][4], bfr[4][2];
#pragma unroll
            for (int im = 0; im < 4; ++im) {
                const int m = mw * 64 + im * 16 + lr;
                const __half* ap = Ab + m * APITCH + ks * 16 + lc * 2;
                a[im][0] = *(const uint32_t*)(ap);
                a[im][1] = *(const uint32_t*)(ap + 8 * APITCH);
                a[im][2] = *(const uint32_t*)(ap + 8);
                a[im][3] = *(const uint32_t*)(ap + 8 * APITCH + 8);
            }
#pragma unroll
            for (int in = 0; in < 4; ++in) {
                const uint32_t addr = bB +
                    ((ks * 16 + (lane & 15)) * BPITCH + nw * 32 + in * 8) * 2;
                asm volatile(
                    "ldmatrix.sync.aligned.m8n8.x2.trans.shared.b16 {%0,%1}, [%2];"
                    : "=r"(bfr[in][0]), "=r"(bfr[in][1]) : "r"(addr));
            }
#pragma unroll
            for (int im = 0; im < 4; ++im)
#pragma unroll
                for (int in = 0; in < 4; ++in) {
                    asm volatile(
                        "mma.sync.aligned.m16n8k16.row.col.f32.f16.f16.f32 "
                        "{%0,%1,%2,%3}, {%4,%5,%6,%7}, {%8,%9}, {%0,%1,%2,%3};"
                        : "+f"(acc[im][in][0]), "+f"(acc[im][in][1]),
                          "+f"(acc[im][in][2]), "+f"(acc[im][in][3])
                        : "r"(a[im][0]), "r"(a[im][1]), "r"(a[im][2]), "r"(a[im][3]),
                          "r"(bfr[in][0]), "r"(bfr[in][1]));
                }
        }

        if (kc < 7) {
            __half* Bd = Bs + (bf ^ 1) * BSZ;
#pragma unroll
            for (int i = 0; i < 4; ++i) {
                const int idx = tid + i * 256;
                const int row = idx >> 5, c4 = idx & 31;
                *(__half2*)(Bd + row * BPITCH + c4 * 4)     = __floats2half2_rn(bv[i].x, bv[i].y);
                *(__half2*)(Bd + row * BPITCH + c4 * 4 + 2) = __floats2half2_rn(bv[i].z, bv[i].w);
            }
        }
    }

    // epilogue: bias + ReLU -> fp16 y
#pragma unroll
    for (int im = 0; im < 4; ++im) {
        const int r0 = m0 + mw * 64 + im * 16 + lr;
        const float bz0 = g_b1[r0], bz1 = g_b1[r0 + 8];
#pragma unroll
        for (int in = 0; in < 4; ++in) {
            const int nc = n0 + nw * 32 + in * 8 + lc * 2;
            __half* p0 = g_yh + ((size_t)(b * CCH + r0)) * HW + nc;
            __half* p1 = p0 + (size_t)8 * HW;
            *(__half2*)p0 = __floats2half2_rn(fmaxf(acc[im][in][0] + bz0, 0.f),
                                              fmaxf(acc[im][in][1] + bz0, 0.f));
            *(__half2*)p1 = __floats2half2_rn(fmaxf(acc[im][in][2] + bz1, 0.f),
                                              fmaxf(acc[im][in][3] + bz1, 0.f));
        }
    }
}

// ---------------------------------------------------------------------------
// K2: refine; y fp16 from GMEM, z fp16 in smem (20 KB), 4 CTAs/SM.
// ---------------------------------------------------------------------------
#define REFINE_SMEM (HW * 2)

__device__ __forceinline__ void row_acc(float z[4], const float* gr,
                                        const float4& L, const float4& C,
                                        const float4& R) {
    const float w6[6] = {L.w, C.x, C.y, C.z, C.w, R.x};
#pragma unroll
    for (int j = 0; j < 4; ++j) {
        z[j] = fmaf(gr[0], w6[j],     z[j]);
        z[j] = fmaf(gr[1], w6[j + 1], z[j]);
        z[j] = fmaf(gr[2], w6[j + 2], z[j]);
    }
}

__global__ __launch_bounds__(256, 4)
void k_refine(const float* __restrict__ x,
              const float* __restrict__ rw, const float* __restrict__ rbias,
              const float* __restrict__ rg, const float* __restrict__ rbeta,
              const float* __restrict__ rmu, const float* __restrict__ rvar,
              float* __restrict__ out,
              float w1, float w2, float w3) {
    extern __shared__ __half zp[];           // z plane, fp16, 20 KB
    uint2* zq2 = (uint2*)zp;                 // 4-half quads

    const int bc = blockIdx.x;
    const int c  = bc & 255;
    const int tid = threadIdx.x;
    const __half* __restrict__ ypl = g_yh + (size_t)bc * HW;
    const uint2* __restrict__ yq  = (const uint2*)ypl;

    const float rs  = rg[c] * rsqrtf(rvar[c] + 1e-5f);
    const float rbb = (rbias[c] - rmu[c]) * rs + rbeta[c];
    float g[3][3];
#pragma unroll
    for (int k = 0; k < 9; ++k) ((float*)g)[k] = rs * __ldg(rw + c * 9 + k);
    const float wts[4] = {0.f, w1, w2, w3};

    // ---- phase Z: 4-row strips, rolling 3-row window, y(fp16) -> z(fp16) ----
    for (int it = tid; it < NG * NQ; it += 256) {
        const int g4 = it / NQ;
        const int wq = it - g4 * NQ;
        const int h0 = g4 << 2;
        const int ql = wq ? wq - 1 : NQ - 1;
        const int qr = (wq == NQ - 1) ? 0 : wq + 1;

        float4 La, Ca, Ra, Lb, Cb, Rb;
        {
            const int rm = (h0 + HH - 1) & (HH - 1);
            La = h4f(yq[rm * NQ + ql]); Ca = h4f(yq[rm * NQ + wq]); Ra = h4f(yq[rm * NQ + qr]);
            Lb = h4f(yq[h0 * NQ + ql]); Cb = h4f(yq[h0 * NQ + wq]); Rb = h4f(yq[h0 * NQ + qr]);
        }
#pragma unroll
        for (int i = 0; i < 4; ++i) {
            const int rn = (h0 + i + 1) & (HH - 1);
            const float4 Lc = h4f(yq[rn * NQ + ql]);
            const float4 Cc = h4f(yq[rn * NQ + wq]);
            const float4 Rc = h4f(yq[rn * NQ + qr]);
            float z[4] = {rbb, rbb, rbb, rbb};
            row_acc(z, g[0], La, Ca, Ra);
            row_acc(z, g[1], Lb, Cb, Rb);
            row_acc(z, g[2], Lc, Cc, Rc);
            uint2 zo;
            *(__half2*)&zo.x = __floats2half2_rn(fmaxf(z[0], 0.f), fmaxf(z[1], 0.f));
            *(__half2*)&zo.y = __floats2half2_rn(fmaxf(z[2], 0.f), fmaxf(z[3], 0.f));
            zq2[(h0 + i) * NQ + wq] = zo;
            La = Lb; Ca = Cb; Ra = Rb;
            Lb = Lc; Cb = Cc; Rb = Rc;
        }
    }
    __syncthreads();

    // ---- phase ACC: 4-row strips, 10-row z column (uint2, cvt on use) ----
    for (int it = tid; it < NG * NQ; it += 256) {
        const int g4 = it / NQ;
        const int wq = it - g4 * NQ;
        const int h0 = g4 << 2;
        const int ql = wq ? wq - 1 : NQ - 1;
        const int qr = (wq == NQ - 1) ? 0 : wq + 1;

        uint2 zv[10];
#pragma unroll
        for (int j = 0; j < 10; ++j)
            zv[j] = zq2[((h0 - 3 + j) & (HH - 1)) * NQ + wq];

#pragma unroll
        for (int i = 0; i < 4; ++i) {
            float acc[4] = {0.f, 0.f, 0.f, 0.f};
#pragma unroll
            for (int s = 1; s <= 3; ++s) {
                const float wt = wts[s];
                const float4 u = h4f(zv[i + 3 - s]);
                const float4 d = h4f(zv[i + 3 + s]);
                acc[0] = fmaf(wt, u.x + d.x, acc[0]);
                acc[1] = fmaf(wt, u.y + d.y, acc[1]);
                acc[2] = fmaf(wt, u.z + d.z, acc[2]);
                acc[3] = fmaf(wt, u.w + d.w, acc[3]);
            }
            const int hh = h0 + i;
            float zr[12];
            *(float4*)(zr)     = h4f(zq2[hh * NQ + ql]);
            *(float4*)(zr + 4) = h4f(zv[i + 3]);
            *(float4*)(zr + 8) = h4f(zq2[hh * NQ + qr]);
#pragma unroll
            for (int s = 1; s <= 3; ++s) {
                const float wt = wts[s];
#pragma unroll
                for (int j = 0; j < 4; ++j)
                    acc[j] = fmaf(wt, zr[4 + j - s] + zr[4 + j + s], acc[j]);
            }
            const size_t base = (size_t)bc * HW + hh * WW + wq * 4;
            const float4 xv = *(const float4*)(x + base);
            float4 o4;
            o4.x = xv.x + acc[0]; o4.y = xv.y + acc[1];
            o4.z = xv.z + acc[2]; o4.w = xv.w + acc[3];
            if (hh >= 1 && hh <= HH - 2 && wq >= 1 && wq <= NQ - 2) {
                *(float4*)(out + base) = o4;
            } else {
#pragma unroll
                for (int j = 0; j < 4; ++j) {
                    const int wj = wq * 4 + j;
                    if (hh >= 1 && hh <= HH - 2 && wj >= 1 && wj <= WW - 2)
                        out[base + j] = ((const float*)&o4)[j];
                }
            }
        }
    }

    // ---- phase BORDER: 444 true-border px, masked formula, y(fp16) ----
    for (int i = tid; i < 2 * WW + 2 * (HH - 2); i += 256) {
        int h, wj;
        if (i < 2 * WW) { h = (i < WW) ? 0 : HH - 1; wj = (i < WW) ? i : i - WW; }
        else { const int j = i - 2 * WW; h = 1 + (j >> 1); wj = (j & 1) ? WW - 1 : 0; }

        const int SHV[12] = {1, 2, 3, -1, -2, -3, 0, 0, 0, 0, 0, 0};
        const int SWV[12] = {0, 0, 0, 0, 0, 0, -1, -2, -3, 1, 2, 3};
        const int AW[12]  = {1, 2, 3, 1, 2, 3, 1, 2, 3, 1, 2, 3};
        const float rv0 = (h >= 1) ? 1.f : 0.f;
        const float rv2 = (h <= HH - 2) ? 1.f : 0.f;
        const float cv0 = (wj >= 1) ? 1.f : 0.f;
        const float cv2 = (wj <= WW - 2) ? 1.f : 0.f;
        float gm[3][3];
#pragma unroll
        for (int kw = 0; kw < 3; ++kw) {
            const float cv = (kw == 0) ? cv0 : (kw == 2) ? cv2 : 1.f;
            gm[0][kw] = g[0][kw] * rv0 * cv;
            gm[1][kw] = g[1][kw] * cv;
            gm[2][kw] = g[2][kw] * rv2 * cv;
        }
        float a = 0.f;
#pragma unroll
        for (int si = 0; si < 12; ++si) {
            const int sh = SHV[si], sw = SWV[si];
            float sum = 0.f;
#pragma unroll
            for (int kh = 0; kh < 3; ++kh)
#pragma unroll
                for (int kw = 0; kw < 3; ++kw) {
                    const int rr = (h + kh - 1 - sh) & (HH - 1);
                    int ccol = wj + kw - 1 - sw;
                    if (ccol < 0) ccol += WW;
                    if (ccol >= WW) ccol -= WW;
                    sum = fmaf(gm[kh][kw], __half2float(ypl[rr * WW + ccol]), sum);
                }
            a = fmaf(wts[AW[si]], fmaxf(sum + rbb, 0.f), a);
        }
        const size_t base = (size_t)bc * HW + h * WW + wj;
        out[base] = x[base] + a;
    }
}

// ---------------------------------------------------------------------------
extern "C" void kernel_launch(void* const* d_in, const int* in_sizes, int n_in,
                              void* d_out, int out_size) {
    const float* x        = (const float*)d_in[0];
    const float* conv_w   = (const float*)d_in[1];
    const float* conv_b   = (const float*)d_in[2];
    const float* bn_gamma = (const float*)d_in[3];
    const float* bn_beta  = (const float*)d_in[4];
    const float* bn_mean  = (const float*)d_in[5];
    const float* bn_var   = (const float*)d_in[6];
    const float* refine_w = (const float*)d_in[7];
    const float* refine_b = (const float*)d_in[8];
    const float* rbn_gamma = (const float*)d_in[9];
    const float* rbn_beta  = (const float*)d_in[10];
    const float* rbn_mean  = (const float*)d_in[11];
    const float* rbn_var   = (const float*)d_in[12];
    float* out = (float*)d_out;

    const double s2 = 2.0 * 1.5 * 1.5;
    const double e1 = exp(-1.0 / s2), e2 = exp(-4.0 / s2), e3 = exp(-9.0 / s2);
    const double wsum = 4.0 * (e1 + e2 + e3);
    const float w1 = (float)(0.5 * e1 / wsum);
    const float w2 = (float)(0.5 * e2 / wsum);
    const float w3 = (float)(0.5 * e3 / wsum);

    cudaFuncSetAttribute(k_gemm, cudaFuncAttributeMaxDynamicSharedMemorySize,
                         GEMM_SMEM);
    cudaFuncSetAttribute(k_refine, cudaFuncAttributeMaxDynamicSharedMemorySize,
                         REFINE_SMEM);

    // order: capture index 3 lands on k_gemm (verify 2-CTA occupancy theory)
    k_nop<<<1, 32>>>();
    k_nop<<<1, 32>>>();

    k_tw<<<CCH, CCH>>>(conv_w, conv_b, bn_gamma, bn_beta, bn_mean, bn_var);

    dim3 gg(HW / BN, CCH / BM, BATCH);   // (80, 2, 8)
    k_gemm<<<gg, 256, GEMM_SMEM>>>(x);

    k_refine<<<BATCH * CCH, 256, REFINE_SMEM>>>(x, refine_w, refine_b,
                                                rbn_gamma, rbn_beta, rbn_mean,
                                                rbn_var, out, w1, w2, w3);
}